// round 8
// baseline (speedup 1.0000x reference)
#include <cuda_runtime.h>
#include <cstdint>

#define BATCH 8
#define NT 1024
#define DIM 768
#define NH 12
#define HD 64
#define SCALE 0.125f
#define NBH (BATCH * NH)

// scratch (allocation-free rule: __device__ globals)
__device__ float g_q[NBH * NT * HD];
__device__ float g_k[NBH * NT * HD];
__device__ float g_v[NBH * NT * HD];
__device__ float g_x[BATCH * NT * DIM];
__device__ float g_tf[BATCH * NT * DIM];          // tf32-rounded tfeat
__device__ float g_w[4 * DIM * DIM];              // tf32-rounded wq,wk,wv,wp
__device__ float g_psum[(size_t)NBH * NT * 8];

// ---------------------------------------------------------------------------
// helpers
// ---------------------------------------------------------------------------
__device__ __forceinline__ uint32_t f2tf(float x) {
    uint32_t r;
    asm("cvt.rna.tf32.f32 %0, %1;" : "=r"(r) : "f"(x));
    return r;
}
__device__ __forceinline__ float round_tf(float x) { return __uint_as_float(f2tf(x)); }

__device__ __forceinline__ void cp16(uint32_t s, const void* g) {
    asm volatile("cp.async.cg.shared.global [%0], [%1], 16;" :: "r"(s), "l"(g));
}
__device__ __forceinline__ void cp4(uint32_t s, const void* g) {
    asm volatile("cp.async.ca.shared.global [%0], [%1], 4;" :: "r"(s), "l"(g));
}
__device__ __forceinline__ void cp_commit() { asm volatile("cp.async.commit_group;"); }
template <int N> __device__ __forceinline__ void cp_wait() {
    asm volatile("cp.async.wait_group %0;" :: "n"(N));
}

__device__ __forceinline__ void mma8(float* c,
                                     uint32_t a0, uint32_t a1, uint32_t a2, uint32_t a3,
                                     uint32_t b0, uint32_t b1) {
    asm volatile(
        "mma.sync.aligned.m16n8k8.row.col.f32.tf32.tf32.f32 "
        "{%0,%1,%2,%3},{%4,%5,%6,%7},{%8,%9},{%0,%1,%2,%3};"
        : "+f"(c[0]), "+f"(c[1]), "+f"(c[2]), "+f"(c[3])
        : "r"(a0), "r"(a1), "r"(a2), "r"(a3), "r"(b0), "r"(b1));
}

// 128x128 block, 8 warps as 2x4 (warp tile 64x32)
template <int STRIDE, int NKS>
__device__ __forceinline__ void compute_tiles(const uint32_t* __restrict__ As,
                                              const uint32_t* __restrict__ Bs,
                                              int wm, int wn, int lane,
                                              float acc[4][4][4]) {
#pragma unroll
    for (int ks = 0; ks < NKS; ++ks) {
        const int col = ks * 8 + (lane & 3);
        uint32_t a[4][4], b[4][2];
#pragma unroll
        for (int mt = 0; mt < 4; ++mt) {
            int r = wm * 64 + mt * 16 + (lane >> 2);
            a[mt][0] = As[r * STRIDE + col];
            a[mt][1] = As[(r + 8) * STRIDE + col];
            a[mt][2] = As[r * STRIDE + col + 4];
            a[mt][3] = As[(r + 8) * STRIDE + col + 4];
        }
#pragma unroll
        for (int nt = 0; nt < 4; ++nt) {
            int n = wn * 32 + nt * 8 + (lane >> 2);
            b[nt][0] = Bs[n * STRIDE + col];
            b[nt][1] = Bs[n * STRIDE + col + 4];
        }
#pragma unroll
        for (int mt = 0; mt < 4; ++mt)
#pragma unroll
            for (int nt = 0; nt < 4; ++nt)
                mma8(acc[mt][nt], a[mt][0], a[mt][1], a[mt][2], a[mt][3],
                     b[nt][0], b[nt][1]);
    }
}

// ---------------------------------------------------------------------------
// 0) tf32 pre-rounding, one launch
// ---------------------------------------------------------------------------
__global__ void round_all_kernel(const float* __restrict__ tfeat,
                                 const float* __restrict__ wq,
                                 const float* __restrict__ wk,
                                 const float* __restrict__ wv,
                                 const float* __restrict__ wp) {
    const int y = blockIdx.y;
    const float* src;
    float* dst;
    int n4;
    if (y == 0) { src = tfeat; dst = g_tf; n4 = BATCH * NT * DIM / 4; }
    else {
        src = (y == 1) ? wq : (y == 2) ? wk : (y == 3) ? wv : wp;
        dst = g_w + (size_t)(y - 1) * DIM * DIM;
        n4 = DIM * DIM / 4;
    }
    for (int i = blockIdx.x * blockDim.x + threadIdx.x; i < n4;
         i += gridDim.x * blockDim.x) {
        float4 v = ((const float4*)src)[i];
        v.x = round_tf(v.x); v.y = round_tf(v.y);
        v.z = round_tf(v.z); v.w = round_tf(v.w);
        ((float4*)dst)[i] = v;
    }
}

// ---------------------------------------------------------------------------
// 1) QKV projection, 3-stage cp.async pipeline. grid (6, 64, 3).
// ---------------------------------------------------------------------------
__global__ __launch_bounds__(256, 2) void qkv_gemm_kernel(
    const float* __restrict__ bq, const float* __restrict__ bk,
    const float* __restrict__ bv)
{
    extern __shared__ uint32_t sm[];
    const uint32_t sbase = (uint32_t)__cvta_generic_to_shared(sm);

    const int z = blockIdx.z;
    const float* A = g_tf;
    const float* W = g_w + (size_t)z * DIM * DIM;
    const float* bias = (z == 0) ? bq : (z == 1) ? bk : bv;
    float* out = (z == 0) ? g_q : (z == 1) ? g_k : g_v;

    const int tid = threadIdx.x;
    const int lane = tid & 31;
    const int wid = tid >> 5;
    const int wm = wid >> 2, wn = wid & 3;
    const int m0 = blockIdx.y * 128;
    const int n0 = blockIdx.x * 128;

    const int srow = tid >> 3;
    const int skq = (tid & 7) << 2;

    auto stage = [&](int buf, int k0) {
        uint32_t aofs = sbase + (uint32_t)(buf * 4608) * 4;
        uint32_t bofs = sbase + (uint32_t)(13824 + buf * 4608) * 4;
#pragma unroll
        for (int u = 0; u < 4; ++u) {
            int row = srow + u * 32;
            cp16(aofs + (uint32_t)(row * 36 + skq) * 4, &A[(size_t)(m0 + row) * DIM + k0 + skq]);
            cp16(bofs + (uint32_t)(row * 36 + skq) * 4, &W[(size_t)(n0 + row) * DIM + k0 + skq]);
        }
        cp_commit();
    };

    float acc[4][4][4] = {};
    stage(0, 0);
    stage(1, 32);
    for (int kt = 0; kt < 24; ++kt) {
        if (kt + 2 < 24) { stage((kt + 2) % 3, (kt + 2) * 32); cp_wait<2>(); }
        else if (kt + 1 < 24) cp_wait<1>();
        else cp_wait<0>();
        __syncthreads();
        const uint32_t* As = sm + (kt % 3) * 4608;
        const uint32_t* Bs = sm + 13824 + (kt % 3) * 4608;
        compute_tiles<36, 4>(As, Bs, wm, wn, lane, acc);
        __syncthreads();
    }

#pragma unroll
    for (int mt = 0; mt < 4; ++mt) {
        int row = m0 + wm * 64 + mt * 16 + (lane >> 2);
        int b0i = row >> 10, t0 = row & 1023;
#pragma unroll
        for (int nt = 0; nt < 4; ++nt) {
            int col = n0 + wn * 32 + nt * 8 + ((lane & 3) << 1);
            int h = col >> 6, d = col & 63;
            float bx = bias[col], by = bias[col + 1];
            float2 lo = make_float2(round_tf(acc[mt][nt][0] + bx), round_tf(acc[mt][nt][1] + by));
            float2 hi = make_float2(round_tf(acc[mt][nt][2] + bx), round_tf(acc[mt][nt][3] + by));
            *(float2*)&out[((size_t)(b0i * NH + h) * NT + t0) * HD + d] = lo;
            *(float2*)&out[((size_t)(b0i * NH + h) * NT + t0 + 8) * HD + d] = hi;
        }
    }
}

// ---------------------------------------------------------------------------
// 2) S = exp(Q K^T * SCALE) + row-sum partials. grid (8, 8, 96).
// ---------------------------------------------------------------------------
__global__ __launch_bounds__(256, 2) void s_exp_kernel(float* __restrict__ attn)
{
    extern __shared__ uint32_t sm[];
    __shared__ float redsum[4][128];
    const uint32_t sbase = (uint32_t)__cvta_generic_to_shared(sm);

    const int tid = threadIdx.x;
    const int lane = tid & 31;
    const int wid = tid >> 5;
    const int wm = wid >> 2, wn = wid & 3;
    const int bh = blockIdx.z;
    const int m0 = blockIdx.y * 128;
    const int n0 = blockIdx.x * 128;

    const float* Q = g_q + (size_t)bh * NT * HD;
    const float* K = g_k + (size_t)bh * NT * HD;

    {
        const uint32_t kofs = sbase + (uint32_t)(128 * 68) * 4;
#pragma unroll
        for (int u = 0; u < 8; ++u) {
            int idx = tid + u * 256;
            int row = idx >> 4;
            int kq = (idx & 15) << 2;
            cp16(sbase + (uint32_t)(row * 68 + kq) * 4, &Q[(size_t)(m0 + row) * HD + kq]);
            cp16(kofs + (uint32_t)(row * 68 + kq) * 4, &K[(size_t)(n0 + row) * HD + kq]);
        }
        cp_commit();
        cp_wait<0>();
        __syncthreads();
    }

    float acc[4][4][4] = {};
    compute_tiles<68, 8>(sm, sm + 128 * 68, wm, wn, lane, acc);

    float rsum[4][2] = {};
    float* ap = attn + (size_t)bh * NT * NT;
#pragma unroll
    for (int mt = 0; mt < 4; ++mt) {
        int row = m0 + wm * 64 + mt * 16 + (lane >> 2);
#pragma unroll
        for (int nt = 0; nt < 4; ++nt) {
            int col = n0 + wn * 32 + nt * 8 + ((lane & 3) << 1);
            float e0 = __expf(acc[mt][nt][0] * SCALE);
            float e1 = __expf(acc[mt][nt][1] * SCALE);
            float e2 = __expf(acc[mt][nt][2] * SCALE);
            float e3 = __expf(acc[mt][nt][3] * SCALE);
            __stcs((float2*)&ap[(size_t)row * NT + col], make_float2(e0, e1));
            __stcs((float2*)&ap[(size_t)(row + 8) * NT + col], make_float2(e2, e3));
            rsum[mt][0] += e0 + e1;
            rsum[mt][1] += e2 + e3;
        }
    }
#pragma unroll
    for (int off = 1; off < 4; off <<= 1)
#pragma unroll
        for (int mt = 0; mt < 4; ++mt) {
            rsum[mt][0] += __shfl_xor_sync(0xffffffffu, rsum[mt][0], off);
            rsum[mt][1] += __shfl_xor_sync(0xffffffffu, rsum[mt][1], off);
        }
    if ((lane & 3) == 0) {
#pragma unroll
        for (int mt = 0; mt < 4; ++mt) {
            int r = wm * 64 + mt * 16 + (lane >> 2);
            redsum[wn][r] = rsum[mt][0];
            redsum[wn][r + 8] = rsum[mt][1];
        }
    }
    __syncthreads();
    if (tid < 128) {
        float s = redsum[0][tid] + redsum[1][tid] + redsum[2][tid] + redsum[3][tid];
        g_psum[((size_t)bh * NT + m0 + tid) * 8 + blockIdx.x] = s;
    }
}

// ---------------------------------------------------------------------------
// 3) O = P V, P staged RAW via cp.async; normalize at use. grid (8, 96).
//    Block 128x64, warps 4x2 (warp tile 32x32).
//    smem words: Praw[2][128*36] at 0/4608; V[2][64*36] at 9216 + buf*2304.
//    Total 13824 w = 55296 B. ~85 regs -> 3 blocks/SM.
// ---------------------------------------------------------------------------
__global__ __launch_bounds__(256) void pv_kernel(float* __restrict__ attn)
{
    extern __shared__ uint32_t sm[];
    __shared__ float invs[128];
    const uint32_t sbase = (uint32_t)__cvta_generic_to_shared(sm);
    float* const smf = (float*)sm;

    const int tid = threadIdx.x;
    const int lane = tid & 31;
    const int wid = tid >> 5;
    const int wm = wid >> 1, wn = wid & 1;
    const int m0 = blockIdx.x * 128;
    const int bh = blockIdx.y;

    for (int r = tid; r < 128; r += 256) {
        const float* pp = &g_psum[((size_t)bh * NT + m0 + r) * 8];
        invs[r] = 1.0f / (pp[0] + pp[1] + pp[2] + pp[3] + pp[4] + pp[5] + pp[6] + pp[7]);
    }
    __syncthreads();

    const int srow = tid >> 3;
    const int skq = (tid & 7) << 2;
    float myinv[4];
#pragma unroll
    for (int u = 0; u < 4; ++u) myinv[u] = invs[srow + u * 32];

    // rowinv for mma fragment rows
    float rvf[2][2];
#pragma unroll
    for (int mt = 0; mt < 2; ++mt) {
        rvf[mt][0] = invs[wm * 32 + mt * 16 + (lane >> 2)];
        rvf[mt][1] = invs[wm * 32 + mt * 16 + (lane >> 2) + 8];
    }

    float* Pg = attn + (size_t)bh * NT * NT;
    const float* V = g_v + (size_t)bh * NT * HD;

    const int vd = tid & 63;
    const int vk = tid >> 6;

    auto stageAll = [&](int buf, int k0) {
        uint32_t pofs = sbase + (uint32_t)(buf * 4608) * 4;
#pragma unroll
        for (int u = 0; u < 4; ++u) {
            int row = srow + u * 32;
            cp16(pofs + (uint32_t)(row * 36 + skq) * 4, &Pg[(size_t)(m0 + row) * NT + k0 + skq]);
        }
        uint32_t vofs = sbase + (uint32_t)(9216 + buf * 2304) * 4;
#pragma unroll
        for (int u = 0; u < 8; ++u) {
            int k = vk + u * 4;
            cp4(vofs + (uint32_t)(vd * 36 + k) * 4, &V[(size_t)(k0 + k) * HD + vd]);
        }
        cp_commit();
    };

    stageAll(0, 0);

    float acc[2][4][4] = {};
    for (int kt = 0; kt < 32; ++kt) {
        const int cur = kt & 1;
        if (kt + 1 < 32) { stageAll((kt + 1) & 1, (kt + 1) * 32); cp_wait<1>(); }
        else cp_wait<0>();
        __syncthreads();

        const float* Pr = smf + cur * 4608;
        // write-back final normalized attn (fire-and-forget stores)
#pragma unroll
        for (int u = 0; u < 4; ++u) {
            int row = srow + u * 32;
            float4 v = *(const float4*)&Pr[row * 36 + skq];
            v.x *= myinv[u]; v.y *= myinv[u]; v.z *= myinv[u]; v.w *= myinv[u];
            __stcs((float4*)&Pg[(size_t)(m0 + row) * NT + kt * 32 + skq], v);
        }

        // O += P V, normalizing a-operand at load
        const uint32_t* Vs = sm + 9216 + cur * 2304;
#pragma unroll
        for (int ks = 0; ks < 4; ++ks) {
            const int col = ks * 8 + (lane & 3);
            uint32_t a[2][4], b[4][2];
#pragma unroll
            for (int mt = 0; mt < 2; ++mt) {
                int r = wm * 32 + mt * 16 + (lane >> 2);
                a[mt][0] = f2tf(Pr[r * 36 + col] * rvf[mt][0]);
                a[mt][1] = f2tf(Pr[(r + 8) * 36 + col] * rvf[mt][1]);
                a[mt][2] = f2tf(Pr[r * 36 + col + 4] * rvf[mt][0]);
                a[mt][3] = f2tf(Pr[(r + 8) * 36 + col + 4] * rvf[mt][1]);
            }
#pragma unroll
            for (int nt = 0; nt < 4; ++nt) {
                int n = wn * 32 + nt * 8 + (lane >> 2);
                b[nt][0] = Vs[n * 36 + col];
                b[nt][1] = Vs[n * 36 + col + 4];
            }
#pragma unroll
            for (int mt = 0; mt < 2; ++mt)
#pragma unroll
                for (int nt = 0; nt < 4; ++nt)
                    mma8(acc[mt][nt], a[mt][0], a[mt][1], a[mt][2], a[mt][3],
                         b[nt][0], b[nt][1]);
        }
        __syncthreads();
    }

    const int b = bh / NH, h = bh % NH;
#pragma unroll
    for (int mt = 0; mt < 2; ++mt) {
        int row = m0 + wm * 32 + mt * 16 + (lane >> 2);
#pragma unroll
        for (int nt = 0; nt < 4; ++nt) {
            int d = wn * 32 + nt * 8 + ((lane & 3) << 1);
            *(float2*)&g_x[((size_t)b * NT + row) * DIM + h * HD + d] =
                make_float2(round_tf(acc[mt][nt][0]), round_tf(acc[mt][nt][1]));
            *(float2*)&g_x[((size_t)b * NT + row + 8) * DIM + h * HD + d] =
                make_float2(round_tf(acc[mt][nt][2]), round_tf(acc[mt][nt][3]));
        }
    }
}

// ---------------------------------------------------------------------------
// 4) output projection, 3-stage cp.async pipeline. grid (6, 64).
// ---------------------------------------------------------------------------
__global__ __launch_bounds__(256, 2) void proj_gemm_kernel(
    const float* __restrict__ bias, float* __restrict__ out)
{
    extern __shared__ uint32_t sm[];
    const uint32_t sbase = (uint32_t)__cvta_generic_to_shared(sm);

    const float* A = g_x;
    const float* W = g_w + (size_t)3 * DIM * DIM;

    const int tid = threadIdx.x;
    const int lane = tid & 31;
    const int wid = tid >> 5;
    const int wm = wid >> 2, wn = wid & 3;
    const int m0 = blockIdx.y * 128;
    const int n0 = blockIdx.x * 128;

    const int srow = tid >> 3;
    const int skq = (tid & 7) << 2;

    auto stage = [&](int buf, int k0) {
        uint32_t aofs = sbase + (uint32_t)(buf * 4608) * 4;
        uint32_t bofs = sbase + (uint32_t)(13824 + buf * 4608) * 4;
#pragma unroll
        for (int u = 0; u < 4; ++u) {
            int row = srow + u * 32;
            cp16(aofs + (uint32_t)(row * 36 + skq) * 4, &A[(size_t)(m0 + row) * DIM + k0 + skq]);
            cp16(bofs + (uint32_t)(row * 36 + skq) * 4, &W[(size_t)(n0 + row) * DIM + k0 + skq]);
        }
        cp_commit();
    };

    float acc[4][4][4] = {};
    stage(0, 0);
    stage(1, 32);
    for (int kt = 0; kt < 24; ++kt) {
        if (kt + 2 < 24) { stage((kt + 2) % 3, (kt + 2) * 32); cp_wait<2>(); }
        else if (kt + 1 < 24) cp_wait<1>();
        else cp_wait<0>();
        __syncthreads();
        const uint32_t* As = sm + (kt % 3) * 4608;
        const uint32_t* Bs = sm + 13824 + (kt % 3) * 4608;
        compute_tiles<36, 4>(As, Bs, wm, wn, lane, acc);
        __syncthreads();
    }

#pragma unroll
    for (int mt = 0; mt < 4; ++mt) {
        int row = m0 + wm * 64 + mt * 16 + (lane >> 2);
#pragma unroll
        for (int nt = 0; nt < 4; ++nt) {
            int col = n0 + wn * 32 + nt * 8 + ((lane & 3) << 1);
            float bx = bias[col], by = bias[col + 1];
            *(float2*)&out[(size_t)row * DIM + col] =
                make_float2(acc[mt][nt][0] + bx, acc[mt][nt][1] + by);
            *(float2*)&out[(size_t)(row + 8) * DIM + col] =
                make_float2(acc[mt][nt][2] + bx, acc[mt][nt][3] + by);
        }
    }
}

// ---------------------------------------------------------------------------

extern "C" void kernel_launch(void* const* d_in, const int* in_sizes, int n_in,
                              void* d_out, int out_size)
{
    const float* tfeat = (const float*)d_in[0];
    const float* wq = (const float*)d_in[1];
    const float* bq = (const float*)d_in[2];
    const float* wk = (const float*)d_in[3];
    const float* bk = (const float*)d_in[4];
    const float* wv = (const float*)d_in[5];
    const float* bv = (const float*)d_in[6];
    const float* wp = (const float*)d_in[7];
    const float* bp = (const float*)d_in[8];

    float* xout = (float*)d_out;
    float* attn_out = (float*)d_out + (size_t)BATCH * NT * DIM;

    round_all_kernel<<<dim3(1024, 5), 256>>>(tfeat, wq, wk, wv, wp);

    cudaFuncSetAttribute(qkv_gemm_kernel, cudaFuncAttributeMaxDynamicSharedMemorySize, 110592);
    cudaFuncSetAttribute(s_exp_kernel, cudaFuncAttributeMaxDynamicSharedMemorySize, 69632);
    cudaFuncSetAttribute(pv_kernel, cudaFuncAttributeMaxDynamicSharedMemorySize, 55296);
    cudaFuncSetAttribute(proj_gemm_kernel, cudaFuncAttributeMaxDynamicSharedMemorySize, 110592);

    qkv_gemm_kernel<<<dim3(DIM / 128, (BATCH * NT) / 128, 3), 256, 110592>>>(bq, bk, bv);
    s_exp_kernel<<<dim3(NT / 128, NT / 128, NBH), 256, 69632>>>(attn_out);
    pv_kernel<<<dim3(NT / 128, NBH), 256, 55296>>>(attn_out);
    proj_gemm_kernel<<<dim3(DIM / 128, (BATCH * NT) / 128), 256, 110592>>>(bp, xout);
}

// round 9
// speedup vs baseline: 1.0196x; 1.0196x over previous
#include <cuda_runtime.h>
#include <cstdint>

#define BATCH 8
#define NT 1024
#define DIM 768
#define NH 12
#define HD 64
#define SCALE 0.125f
#define NBH (BATCH * NH)

// scratch (allocation-free rule: __device__ globals)
__device__ float g_q[NBH * NT * HD];
__device__ float g_k[NBH * NT * HD];
__device__ float g_v[NBH * NT * HD];
__device__ float g_x[BATCH * NT * DIM];
__device__ float g_tf[BATCH * NT * DIM];          // tf32-rounded tfeat
__device__ float g_w[4 * DIM * DIM];              // tf32-rounded wq,wk,wv,wp
__device__ float g_psum[(size_t)NBH * NT * 8];

// ---------------------------------------------------------------------------
// helpers
// ---------------------------------------------------------------------------
__device__ __forceinline__ uint32_t f2tf(float x) {
    uint32_t r;
    asm("cvt.rna.tf32.f32 %0, %1;" : "=r"(r) : "f"(x));
    return r;
}
__device__ __forceinline__ float round_tf(float x) { return __uint_as_float(f2tf(x)); }

__device__ __forceinline__ void cp16(uint32_t s, const void* g) {
    asm volatile("cp.async.cg.shared.global [%0], [%1], 16;" :: "r"(s), "l"(g));
}
__device__ __forceinline__ void cp4(uint32_t s, const void* g) {
    asm volatile("cp.async.ca.shared.global [%0], [%1], 4;" :: "r"(s), "l"(g));
}
__device__ __forceinline__ void cp_commit() { asm volatile("cp.async.commit_group;"); }
template <int N> __device__ __forceinline__ void cp_wait() {
    asm volatile("cp.async.wait_group %0;" :: "n"(N));
}

__device__ __forceinline__ void mma8(float* c,
                                     uint32_t a0, uint32_t a1, uint32_t a2, uint32_t a3,
                                     uint32_t b0, uint32_t b1) {
    asm volatile(
        "mma.sync.aligned.m16n8k8.row.col.f32.tf32.tf32.f32 "
        "{%0,%1,%2,%3},{%4,%5,%6,%7},{%8,%9},{%0,%1,%2,%3};"
        : "+f"(c[0]), "+f"(c[1]), "+f"(c[2]), "+f"(c[3])
        : "r"(a0), "r"(a1), "r"(a2), "r"(a3), "r"(b0), "r"(b1));
}

// 128x128 block, 8 warps as 2x4 (warp tile 64x32)
template <int STRIDE, int NKS>
__device__ __forceinline__ void compute_tiles(const uint32_t* __restrict__ As,
                                              const uint32_t* __restrict__ Bs,
                                              int wm, int wn, int lane,
                                              float acc[4][4][4]) {
#pragma unroll
    for (int ks = 0; ks < NKS; ++ks) {
        const int col = ks * 8 + (lane & 3);
        uint32_t a[4][4], b[4][2];
#pragma unroll
        for (int mt = 0; mt < 4; ++mt) {
            int r = wm * 64 + mt * 16 + (lane >> 2);
            a[mt][0] = As[r * STRIDE + col];
            a[mt][1] = As[(r + 8) * STRIDE + col];
            a[mt][2] = As[r * STRIDE + col + 4];
            a[mt][3] = As[(r + 8) * STRIDE + col + 4];
        }
#pragma unroll
        for (int nt = 0; nt < 4; ++nt) {
            int n = wn * 32 + nt * 8 + (lane >> 2);
            b[nt][0] = Bs[n * STRIDE + col];
            b[nt][1] = Bs[n * STRIDE + col + 4];
        }
#pragma unroll
        for (int mt = 0; mt < 4; ++mt)
#pragma unroll
            for (int nt = 0; nt < 4; ++nt)
                mma8(acc[mt][nt], a[mt][0], a[mt][1], a[mt][2], a[mt][3],
                     b[nt][0], b[nt][1]);
    }
}

// ---------------------------------------------------------------------------
// 0) tf32 pre-rounding, one launch
// ---------------------------------------------------------------------------
__global__ void round_all_kernel(const float* __restrict__ tfeat,
                                 const float* __restrict__ wq,
                                 const float* __restrict__ wk,
                                 const float* __restrict__ wv,
                                 const float* __restrict__ wp) {
    const int y = blockIdx.y;
    const float* src;
    float* dst;
    int n4;
    if (y == 0) { src = tfeat; dst = g_tf; n4 = BATCH * NT * DIM / 4; }
    else {
        src = (y == 1) ? wq : (y == 2) ? wk : (y == 3) ? wv : wp;
        dst = g_w + (size_t)(y - 1) * DIM * DIM;
        n4 = DIM * DIM / 4;
    }
    for (int i = blockIdx.x * blockDim.x + threadIdx.x; i < n4;
         i += gridDim.x * blockDim.x) {
        float4 v = ((const float4*)src)[i];
        v.x = round_tf(v.x); v.y = round_tf(v.y);
        v.z = round_tf(v.z); v.w = round_tf(v.w);
        ((float4*)dst)[i] = v;
    }
}

// ---------------------------------------------------------------------------
// 1) QKV projection, 3-stage cp.async pipeline. grid (6, 64, 3).
// ---------------------------------------------------------------------------
__global__ __launch_bounds__(256, 2) void qkv_gemm_kernel(
    const float* __restrict__ bq, const float* __restrict__ bk,
    const float* __restrict__ bv)
{
    extern __shared__ uint32_t sm[];
    const uint32_t sbase = (uint32_t)__cvta_generic_to_shared(sm);

    const int z = blockIdx.z;
    const float* A = g_tf;
    const float* W = g_w + (size_t)z * DIM * DIM;
    const float* bias = (z == 0) ? bq : (z == 1) ? bk : bv;
    float* out = (z == 0) ? g_q : (z == 1) ? g_k : g_v;

    const int tid = threadIdx.x;
    const int lane = tid & 31;
    const int wid = tid >> 5;
    const int wm = wid >> 2, wn = wid & 3;
    const int m0 = blockIdx.y * 128;
    const int n0 = blockIdx.x * 128;

    const int srow = tid >> 3;
    const int skq = (tid & 7) << 2;

    auto stage = [&](int buf, int k0) {
        uint32_t aofs = sbase + (uint32_t)(buf * 4608) * 4;
        uint32_t bofs = sbase + (uint32_t)(13824 + buf * 4608) * 4;
#pragma unroll
        for (int u = 0; u < 4; ++u) {
            int row = srow + u * 32;
            cp16(aofs + (uint32_t)(row * 36 + skq) * 4, &A[(size_t)(m0 + row) * DIM + k0 + skq]);
            cp16(bofs + (uint32_t)(row * 36 + skq) * 4, &W[(size_t)(n0 + row) * DIM + k0 + skq]);
        }
        cp_commit();
    };

    float acc[4][4][4] = {};
    stage(0, 0);
    stage(1, 32);
    for (int kt = 0; kt < 24; ++kt) {
        if (kt + 2 < 24) { stage((kt + 2) % 3, (kt + 2) * 32); cp_wait<2>(); }
        else if (kt + 1 < 24) cp_wait<1>();
        else cp_wait<0>();
        __syncthreads();
        const uint32_t* As = sm + (kt % 3) * 4608;
        const uint32_t* Bs = sm + 13824 + (kt % 3) * 4608;
        compute_tiles<36, 4>(As, Bs, wm, wn, lane, acc);
        __syncthreads();
    }

#pragma unroll
    for (int mt = 0; mt < 4; ++mt) {
        int row = m0 + wm * 64 + mt * 16 + (lane >> 2);
        int b0i = row >> 10, t0 = row & 1023;
#pragma unroll
        for (int nt = 0; nt < 4; ++nt) {
            int col = n0 + wn * 32 + nt * 8 + ((lane & 3) << 1);
            int h = col >> 6, d = col & 63;
            float bx = bias[col], by = bias[col + 1];
            float2 lo = make_float2(round_tf(acc[mt][nt][0] + bx), round_tf(acc[mt][nt][1] + by));
            float2 hi = make_float2(round_tf(acc[mt][nt][2] + bx), round_tf(acc[mt][nt][3] + by));
            *(float2*)&out[((size_t)(b0i * NH + h) * NT + t0) * HD + d] = lo;
            *(float2*)&out[((size_t)(b0i * NH + h) * NT + t0 + 8) * HD + d] = hi;
        }
    }
}

// ---------------------------------------------------------------------------
// 2) S = exp(Q K^T * SCALE) + row-sum partials. grid (8, 8, 96).
//    Plain stores (keep tail resident in L2 for pv).
// ---------------------------------------------------------------------------
__global__ __launch_bounds__(256, 2) void s_exp_kernel(float* __restrict__ attn)
{
    extern __shared__ uint32_t sm[];
    __shared__ float redsum[4][128];
    const uint32_t sbase = (uint32_t)__cvta_generic_to_shared(sm);

    const int tid = threadIdx.x;
    const int lane = tid & 31;
    const int wid = tid >> 5;
    const int wm = wid >> 2, wn = wid & 3;
    const int bh = blockIdx.z;
    const int m0 = blockIdx.y * 128;
    const int n0 = blockIdx.x * 128;

    const float* Q = g_q + (size_t)bh * NT * HD;
    const float* K = g_k + (size_t)bh * NT * HD;

    {
        const uint32_t kofs = sbase + (uint32_t)(128 * 68) * 4;
#pragma unroll
        for (int u = 0; u < 8; ++u) {
            int idx = tid + u * 256;
            int row = idx >> 4;
            int kq = (idx & 15) << 2;
            cp16(sbase + (uint32_t)(row * 68 + kq) * 4, &Q[(size_t)(m0 + row) * HD + kq]);
            cp16(kofs + (uint32_t)(row * 68 + kq) * 4, &K[(size_t)(n0 + row) * HD + kq]);
        }
        cp_commit();
        cp_wait<0>();
        __syncthreads();
    }

    float acc[4][4][4] = {};
    compute_tiles<68, 8>(sm, sm + 128 * 68, wm, wn, lane, acc);

    float rsum[4][2] = {};
    float* ap = attn + (size_t)bh * NT * NT;
#pragma unroll
    for (int mt = 0; mt < 4; ++mt) {
        int row = m0 + wm * 64 + mt * 16 + (lane >> 2);
#pragma unroll
        for (int nt = 0; nt < 4; ++nt) {
            int col = n0 + wn * 32 + nt * 8 + ((lane & 3) << 1);
            float e0 = __expf(acc[mt][nt][0] * SCALE);
            float e1 = __expf(acc[mt][nt][1] * SCALE);
            float e2 = __expf(acc[mt][nt][2] * SCALE);
            float e3 = __expf(acc[mt][nt][3] * SCALE);
            *(float2*)&ap[(size_t)row * NT + col] = make_float2(e0, e1);
            *(float2*)&ap[(size_t)(row + 8) * NT + col] = make_float2(e2, e3);
            rsum[mt][0] += e0 + e1;
            rsum[mt][1] += e2 + e3;
        }
    }
#pragma unroll
    for (int off = 1; off < 4; off <<= 1)
#pragma unroll
        for (int mt = 0; mt < 4; ++mt) {
            rsum[mt][0] += __shfl_xor_sync(0xffffffffu, rsum[mt][0], off);
            rsum[mt][1] += __shfl_xor_sync(0xffffffffu, rsum[mt][1], off);
        }
    if ((lane & 3) == 0) {
#pragma unroll
        for (int mt = 0; mt < 4; ++mt) {
            int r = wm * 64 + mt * 16 + (lane >> 2);
            redsum[wn][r] = rsum[mt][0];
            redsum[wn][r + 8] = rsum[mt][1];
        }
    }
    __syncthreads();
    if (tid < 128) {
        float s = redsum[0][tid] + redsum[1][tid] + redsum[2][tid] + redsum[3][tid];
        g_psum[((size_t)bh * NT + m0 + tid) * 8 + blockIdx.x] = s;
    }
}

// ---------------------------------------------------------------------------
// 3) O = P V with in-place normalization. grid (8, 96), bh REVERSED for L2
//    temporal reuse of s_exp's tail. Block 128x64, warps 4x2 (32x32 tiles).
// ---------------------------------------------------------------------------
__global__ __launch_bounds__(256, 2) void pv_kernel(float* __restrict__ attn)
{
    extern __shared__ uint32_t sm[];
    __shared__ float invs[128];
    const uint32_t sbase = (uint32_t)__cvta_generic_to_shared(sm);

    const int tid = threadIdx.x;
    const int lane = tid & 31;
    const int wid = tid >> 5;
    const int wm = wid >> 1, wn = wid & 1;
    const int m0 = blockIdx.x * 128;
    const int bh = (NBH - 1) - blockIdx.y;      // reverse: read s_exp's最 recent writes first

    for (int r = tid; r < 128; r += 256) {
        const float* pp = &g_psum[((size_t)bh * NT + m0 + r) * 8];
        invs[r] = 1.0f / (pp[0] + pp[1] + pp[2] + pp[3] + pp[4] + pp[5] + pp[6] + pp[7]);
    }
    __syncthreads();

    const int srow = tid >> 3;
    const int skq = (tid & 7) << 2;
    float myinv[4];
#pragma unroll
    for (int u = 0; u < 4; ++u) myinv[u] = invs[srow + u * 32];

    float* Pg = attn + (size_t)bh * NT * NT;
    const float* V = g_v + (size_t)bh * NT * HD;

    const int vd = tid & 63;
    const int vk = tid >> 6;

    auto stageV = [&](int buf, int k0) {
        uint32_t vofs = sbase + (uint32_t)(9216 + buf * 2304) * 4;
#pragma unroll
        for (int u = 0; u < 8; ++u) {
            int k = vk + u * 4;
            cp4(vofs + (uint32_t)(vd * 36 + k) * 4, &V[(size_t)(k0 + k) * HD + vd]);
        }
        cp_commit();
    };

    float4 pf[4], pf2[4];
#pragma unroll
    for (int u = 0; u < 4; ++u)
        pf[u] = *(const float4*)&Pg[(size_t)(m0 + srow + u * 32) * NT + skq];
    stageV(0, 0);

    float acc[2][4][4] = {};
    for (int kt = 0; kt < 32; ++kt) {
        const int cur = kt & 1;
        uint32_t* Pb = sm + cur * 4608;
        float4 vn[4];
#pragma unroll
        for (int u = 0; u < 4; ++u) {
            int row = srow + u * 32;
            float4 v = pf[u];
            v.x *= myinv[u]; v.y *= myinv[u]; v.z *= myinv[u]; v.w *= myinv[u];
            vn[u] = v;
            uint4 t;
            t.x = f2tf(v.x); t.y = f2tf(v.y); t.z = f2tf(v.z); t.w = f2tf(v.w);
            *(uint4*)&Pb[row * 36 + skq] = t;
        }
#pragma unroll
        for (int u = 0; u < 4; ++u) {
            int row = srow + u * 32;
            __stcs((float4*)&Pg[(size_t)(m0 + row) * NT + kt * 32 + skq], vn[u]);
        }
        if (kt + 1 < 32) {
            stageV((kt + 1) & 1, (kt + 1) * 32);
#pragma unroll
            for (int u = 0; u < 4; ++u)
                pf2[u] = *(const float4*)&Pg[(size_t)(m0 + srow + u * 32) * NT + (kt + 1) * 32 + skq];
            cp_wait<1>();
        } else {
            cp_wait<0>();
        }
        __syncthreads();

        const uint32_t* Ps = sm + cur * 4608;
        const uint32_t* Vs = sm + 9216 + cur * 2304;
#pragma unroll
        for (int ks = 0; ks < 4; ++ks) {
            const int col = ks * 8 + (lane & 3);
            uint32_t a[2][4], b[4][2];
#pragma unroll
            for (int mt = 0; mt < 2; ++mt) {
                int r = wm * 32 + mt * 16 + (lane >> 2);
                a[mt][0] = Ps[r * 36 + col];
                a[mt][1] = Ps[(r + 8) * 36 + col];
                a[mt][2] = Ps[r * 36 + col + 4];
                a[mt][3] = Ps[(r + 8) * 36 + col + 4];
            }
#pragma unroll
            for (int nt = 0; nt < 4; ++nt) {
                int n = wn * 32 + nt * 8 + (lane >> 2);
                b[nt][0] = Vs[n * 36 + col];
                b[nt][1] = Vs[n * 36 + col + 4];
            }
#pragma unroll
            for (int mt = 0; mt < 2; ++mt)
#pragma unroll
                for (int nt = 0; nt < 4; ++nt)
                    mma8(acc[mt][nt], a[mt][0], a[mt][1], a[mt][2], a[mt][3],
                         b[nt][0], b[nt][1]);
        }
        __syncthreads();
#pragma unroll
        for (int u = 0; u < 4; ++u) pf[u] = pf2[u];
    }

    const int b = bh / NH, h = bh % NH;
#pragma unroll
    for (int mt = 0; mt < 2; ++mt) {
        int row = m0 + wm * 32 + mt * 16 + (lane >> 2);
#pragma unroll
        for (int nt = 0; nt < 4; ++nt) {
            int d = wn * 32 + nt * 8 + ((lane & 3) << 1);
            *(float2*)&g_x[((size_t)b * NT + row) * DIM + h * HD + d] =
                make_float2(round_tf(acc[mt][nt][0]), round_tf(acc[mt][nt][1]));
            *(float2*)&g_x[((size_t)b * NT + row + 8) * DIM + h * HD + d] =
                make_float2(round_tf(acc[mt][nt][2]), round_tf(acc[mt][nt][3]));
        }
    }
}

// ---------------------------------------------------------------------------
// 4) output projection, 3-stage cp.async pipeline. grid (6, 64).
// ---------------------------------------------------------------------------
__global__ __launch_bounds__(256, 2) void proj_gemm_kernel(
    const float* __restrict__ bias, float* __restrict__ out)
{
    extern __shared__ uint32_t sm[];
    const uint32_t sbase = (uint32_t)__cvta_generic_to_shared(sm);

    const float* A = g_x;
    const float* W = g_w + (size_t)3 * DIM * DIM;

    const int tid = threadIdx.x;
    const int lane = tid & 31;
    const int wid = tid >> 5;
    const int wm = wid >> 2, wn = wid & 3;
    const int m0 = blockIdx.y * 128;
    const int n0 = blockIdx.x * 128;

    const int srow = tid >> 3;
    const int skq = (tid & 7) << 2;

    auto stage = [&](int buf, int k0) {
        uint32_t aofs = sbase + (uint32_t)(buf * 4608) * 4;
        uint32_t bofs = sbase + (uint32_t)(13824 + buf * 4608) * 4;
#pragma unroll
        for (int u = 0; u < 4; ++u) {
            int row = srow + u * 32;
            cp16(aofs + (uint32_t)(row * 36 + skq) * 4, &A[(size_t)(m0 + row) * DIM + k0 + skq]);
            cp16(bofs + (uint32_t)(row * 36 + skq) * 4, &W[(size_t)(n0 + row) * DIM + k0 + skq]);
        }
        cp_commit();
    };

    float acc[4][4][4] = {};
    stage(0, 0);
    stage(1, 32);
    for (int kt = 0; kt < 24; ++kt) {
        if (kt + 2 < 24) { stage((kt + 2) % 3, (kt + 2) * 32); cp_wait<2>(); }
        else if (kt + 1 < 24) cp_wait<1>();
        else cp_wait<0>();
        __syncthreads();
        const uint32_t* As = sm + (kt % 3) * 4608;
        const uint32_t* Bs = sm + 13824 + (kt % 3) * 4608;
        compute_tiles<36, 4>(As, Bs, wm, wn, lane, acc);
        __syncthreads();
    }

#pragma unroll
    for (int mt = 0; mt < 4; ++mt) {
        int row = m0 + wm * 64 + mt * 16 + (lane >> 2);
#pragma unroll
        for (int nt = 0; nt < 4; ++nt) {
            int col = n0 + wn * 32 + nt * 8 + ((lane & 3) << 1);
            float bx = bias[col], by = bias[col + 1];
            *(float2*)&out[(size_t)row * DIM + col] =
                make_float2(acc[mt][nt][0] + bx, acc[mt][nt][1] + by);
            *(float2*)&out[(size_t)(row + 8) * DIM + col] =
                make_float2(acc[mt][nt][2] + bx, acc[mt][nt][3] + by);
        }
    }
}

// ---------------------------------------------------------------------------

extern "C" void kernel_launch(void* const* d_in, const int* in_sizes, int n_in,
                              void* d_out, int out_size)
{
    const float* tfeat = (const float*)d_in[0];
    const float* wq = (const float*)d_in[1];
    const float* bq = (const float*)d_in[2];
    const float* wk = (const float*)d_in[3];
    const float* bk = (const float*)d_in[4];
    const float* wv = (const float*)d_in[5];
    const float* bv = (const float*)d_in[6];
    const float* wp = (const float*)d_in[7];
    const float* bp = (const float*)d_in[8];

    float* xout = (float*)d_out;
    float* attn_out = (float*)d_out + (size_t)BATCH * NT * DIM;

    round_all_kernel<<<dim3(1024, 5), 256>>>(tfeat, wq, wk, wv, wp);

    cudaFuncSetAttribute(qkv_gemm_kernel, cudaFuncAttributeMaxDynamicSharedMemorySize, 110592);
    cudaFuncSetAttribute(s_exp_kernel, cudaFuncAttributeMaxDynamicSharedMemorySize, 69632);
    cudaFuncSetAttribute(pv_kernel, cudaFuncAttributeMaxDynamicSharedMemorySize, 55296);
    cudaFuncSetAttribute(proj_gemm_kernel, cudaFuncAttributeMaxDynamicSharedMemorySize, 110592);

    qkv_gemm_kernel<<<dim3(DIM / 128, (BATCH * NT) / 128, 3), 256, 110592>>>(bq, bk, bv);
    s_exp_kernel<<<dim3(NT / 128, NT / 128, NBH), 256, 69632>>>(attn_out);
    pv_kernel<<<dim3(NT / 128, NBH), 256, 55296>>>(attn_out);
    proj_gemm_kernel<<<dim3(DIM / 128, (BATCH * NT) / 128), 256, 110592>>>(bp, xout);
}

// round 11
// speedup vs baseline: 1.0524x; 1.0321x over previous
#include <cuda_runtime.h>
#include <cuda_fp16.h>
#include <cstdint>

#define BATCH 8
#define NT 1024
#define DIM 768
#define NH 12
#define HD 64
#define SCALE 0.125f
#define NBH (BATCH * NH)

// scratch (allocation-free rule: __device__ globals)
__device__ float g_q[NBH * NT * HD];
__device__ float g_k[NBH * NT * HD];
__device__ float g_v[NBH * NT * HD];
__device__ float g_x[BATCH * NT * DIM];
__device__ float g_tf[BATCH * NT * DIM];              // tf32-rounded tfeat
__device__ float g_w[4 * DIM * DIM];                  // tf32-rounded weights
__device__ float g_psum[(size_t)NBH * NT * 8];
__device__ __half g_p[(size_t)NBH * NT * NT];         // unnormalized exp scores, fp16

// ---------------------------------------------------------------------------
// helpers
// ---------------------------------------------------------------------------
__device__ __forceinline__ uint32_t f2tf(float x) {
    uint32_t r;
    asm("cvt.rna.tf32.f32 %0, %1;" : "=r"(r) : "f"(x));
    return r;
}
__device__ __forceinline__ float round_tf(float x) { return __uint_as_float(f2tf(x)); }

__device__ __forceinline__ uint32_t h2_as_u32(__half2 h) {
    union { __half2 h2; uint32_t u; } cvt;
    cvt.h2 = h;
    return cvt.u;
}

__device__ __forceinline__ void cp16(uint32_t s, const void* g) {
    asm volatile("cp.async.cg.shared.global [%0], [%1], 16;" :: "r"(s), "l"(g));
}
__device__ __forceinline__ void cp4(uint32_t s, const void* g) {
    asm volatile("cp.async.ca.shared.global [%0], [%1], 4;" :: "r"(s), "l"(g));
}
__device__ __forceinline__ void cp_commit() { asm volatile("cp.async.commit_group;"); }
template <int N> __device__ __forceinline__ void cp_wait() {
    asm volatile("cp.async.wait_group %0;" :: "n"(N));
}

__device__ __forceinline__ void mma8(float* c,
                                     uint32_t a0, uint32_t a1, uint32_t a2, uint32_t a3,
                                     uint32_t b0, uint32_t b1) {
    asm volatile(
        "mma.sync.aligned.m16n8k8.row.col.f32.tf32.tf32.f32 "
        "{%0,%1,%2,%3},{%4,%5,%6,%7},{%8,%9},{%0,%1,%2,%3};"
        : "+f"(c[0]), "+f"(c[1]), "+f"(c[2]), "+f"(c[3])
        : "r"(a0), "r"(a1), "r"(a2), "r"(a3), "r"(b0), "r"(b1));
}

__device__ __forceinline__ void mma16(float* c,
                                      uint32_t a0, uint32_t a1, uint32_t a2, uint32_t a3,
                                      uint32_t b0, uint32_t b1) {
    asm volatile(
        "mma.sync.aligned.m16n8k16.row.col.f32.f16.f16.f32 "
        "{%0,%1,%2,%3},{%4,%5,%6,%7},{%8,%9},{%0,%1,%2,%3};"
        : "+f"(c[0]), "+f"(c[1]), "+f"(c[2]), "+f"(c[3])
        : "r"(a0), "r"(a1), "r"(a2), "r"(a3), "r"(b0), "r"(b1));
}

// 128x128 block, 8 warps as 2x4 (warp tile 64x32)
template <int STRIDE, int NKS>
__device__ __forceinline__ void compute_tiles(const uint32_t* __restrict__ As,
                                              const uint32_t* __restrict__ Bs,
                                              int wm, int wn, int lane,
                                              float acc[4][4][4]) {
#pragma unroll
    for (int ks = 0; ks < NKS; ++ks) {
        const int col = ks * 8 + (lane & 3);
        uint32_t a[4][4], b[4][2];
#pragma unroll
        for (int mt = 0; mt < 4; ++mt) {
            int r = wm * 64 + mt * 16 + (lane >> 2);
            a[mt][0] = As[r * STRIDE + col];
            a[mt][1] = As[(r + 8) * STRIDE + col];
            a[mt][2] = As[r * STRIDE + col + 4];
            a[mt][3] = As[(r + 8) * STRIDE + col + 4];
        }
#pragma unroll
        for (int nt = 0; nt < 4; ++nt) {
            int n = wn * 32 + nt * 8 + (lane >> 2);
            b[nt][0] = Bs[n * STRIDE + col];
            b[nt][1] = Bs[n * STRIDE + col + 4];
        }
#pragma unroll
        for (int mt = 0; mt < 4; ++mt)
#pragma unroll
            for (int nt = 0; nt < 4; ++nt)
                mma8(acc[mt][nt], a[mt][0], a[mt][1], a[mt][2], a[mt][3],
                     b[nt][0], b[nt][1]);
    }
}

// ---------------------------------------------------------------------------
// 0) tf32 pre-rounding, one launch
// ---------------------------------------------------------------------------
__global__ void round_all_kernel(const float* __restrict__ tfeat,
                                 const float* __restrict__ wq,
                                 const float* __restrict__ wk,
                                 const float* __restrict__ wv,
                                 const float* __restrict__ wp) {
    const int y = blockIdx.y;
    const float* src;
    float* dst;
    int n4;
    if (y == 0) { src = tfeat; dst = g_tf; n4 = BATCH * NT * DIM / 4; }
    else {
        src = (y == 1) ? wq : (y == 2) ? wk : (y == 3) ? wv : wp;
        dst = g_w + (size_t)(y - 1) * DIM * DIM;
        n4 = DIM * DIM / 4;
    }
    for (int i = blockIdx.x * blockDim.x + threadIdx.x; i < n4;
         i += gridDim.x * blockDim.x) {
        float4 v = ((const float4*)src)[i];
        v.x = round_tf(v.x); v.y = round_tf(v.y);
        v.z = round_tf(v.z); v.w = round_tf(v.w);
        ((float4*)dst)[i] = v;
    }
}

// ---------------------------------------------------------------------------
// 1) QKV projection, 3-stage cp.async pipeline. grid (6, 64, 3).
// ---------------------------------------------------------------------------
__global__ __launch_bounds__(256, 2) void qkv_gemm_kernel(
    const float* __restrict__ bq, const float* __restrict__ bk,
    const float* __restrict__ bv)
{
    extern __shared__ uint32_t sm[];
    const uint32_t sbase = (uint32_t)__cvta_generic_to_shared(sm);

    const int z = blockIdx.z;
    const float* A = g_tf;
    const float* W = g_w + (size_t)z * DIM * DIM;
    const float* bias = (z == 0) ? bq : (z == 1) ? bk : bv;
    float* out = (z == 0) ? g_q : (z == 1) ? g_k : g_v;

    const int tid = threadIdx.x;
    const int lane = tid & 31;
    const int wid = tid >> 5;
    const int wm = wid >> 2, wn = wid & 3;
    const int m0 = blockIdx.y * 128;
    const int n0 = blockIdx.x * 128;

    const int srow = tid >> 3;
    const int skq = (tid & 7) << 2;

    auto stage = [&](int buf, int k0) {
        uint32_t aofs = sbase + (uint32_t)(buf * 4608) * 4;
        uint32_t bofs = sbase + (uint32_t)(13824 + buf * 4608) * 4;
#pragma unroll
        for (int u = 0; u < 4; ++u) {
            int row = srow + u * 32;
            cp16(aofs + (uint32_t)(row * 36 + skq) * 4, &A[(size_t)(m0 + row) * DIM + k0 + skq]);
            cp16(bofs + (uint32_t)(row * 36 + skq) * 4, &W[(size_t)(n0 + row) * DIM + k0 + skq]);
        }
        cp_commit();
    };

    float acc[4][4][4] = {};
    stage(0, 0);
    stage(1, 32);
    for (int kt = 0; kt < 24; ++kt) {
        if (kt + 2 < 24) { stage((kt + 2) % 3, (kt + 2) * 32); cp_wait<2>(); }
        else if (kt + 1 < 24) cp_wait<1>();
        else cp_wait<0>();
        __syncthreads();
        const uint32_t* As = sm + (kt % 3) * 4608;
        const uint32_t* Bs = sm + 13824 + (kt % 3) * 4608;
        compute_tiles<36, 4>(As, Bs, wm, wn, lane, acc);
        __syncthreads();
    }

#pragma unroll
    for (int mt = 0; mt < 4; ++mt) {
        int row = m0 + wm * 64 + mt * 16 + (lane >> 2);
        int b0i = row >> 10, t0 = row & 1023;
#pragma unroll
        for (int nt = 0; nt < 4; ++nt) {
            int col = n0 + wn * 32 + nt * 8 + ((lane & 3) << 1);
            int h = col >> 6, d = col & 63;
            float bx = bias[col], by = bias[col + 1];
            float2 lo = make_float2(round_tf(acc[mt][nt][0] + bx), round_tf(acc[mt][nt][1] + by));
            float2 hi = make_float2(round_tf(acc[mt][nt][2] + bx), round_tf(acc[mt][nt][3] + by));
            *(float2*)&out[((size_t)(b0i * NH + h) * NT + t0) * HD + d] = lo;
            *(float2*)&out[((size_t)(b0i * NH + h) * NT + t0 + 8) * HD + d] = hi;
        }
    }
}

// ---------------------------------------------------------------------------
// 2) S: exp(Q K^T * SCALE) -> fp16 g_p (unnormalized) + row-sum partials.
//    grid (8, 8, 96).
// ---------------------------------------------------------------------------
__global__ __launch_bounds__(256, 2) void s_exp_kernel()
{
    extern __shared__ uint32_t sm[];
    __shared__ float redsum[4][128];
    const uint32_t sbase = (uint32_t)__cvta_generic_to_shared(sm);

    const int tid = threadIdx.x;
    const int lane = tid & 31;
    const int wid = tid >> 5;
    const int wm = wid >> 2, wn = wid & 3;
    const int bh = blockIdx.z;
    const int m0 = blockIdx.y * 128;
    const int n0 = blockIdx.x * 128;

    const float* Q = g_q + (size_t)bh * NT * HD;
    const float* K = g_k + (size_t)bh * NT * HD;

    {
        const uint32_t kofs = sbase + (uint32_t)(128 * 68) * 4;
#pragma unroll
        for (int u = 0; u < 8; ++u) {
            int idx = tid + u * 256;
            int row = idx >> 4;
            int kq = (idx & 15) << 2;
            cp16(sbase + (uint32_t)(row * 68 + kq) * 4, &Q[(size_t)(m0 + row) * HD + kq]);
            cp16(kofs + (uint32_t)(row * 68 + kq) * 4, &K[(size_t)(n0 + row) * HD + kq]);
        }
        cp_commit();
        cp_wait<0>();
        __syncthreads();
    }

    float acc[4][4][4] = {};
    compute_tiles<68, 8>(sm, sm + 128 * 68, wm, wn, lane, acc);

    float rsum[4][2] = {};
    __half* pp = g_p + (size_t)bh * NT * NT;
#pragma unroll
    for (int mt = 0; mt < 4; ++mt) {
        int row = m0 + wm * 64 + mt * 16 + (lane >> 2);
#pragma unroll
        for (int nt = 0; nt < 4; ++nt) {
            int col = n0 + wn * 32 + nt * 8 + ((lane & 3) << 1);
            float e0 = __expf(acc[mt][nt][0] * SCALE);
            float e1 = __expf(acc[mt][nt][1] * SCALE);
            float e2 = __expf(acc[mt][nt][2] * SCALE);
            float e3 = __expf(acc[mt][nt][3] * SCALE);
            *(__half2*)&pp[(size_t)row * NT + col] = __floats2half2_rn(e0, e1);
            *(__half2*)&pp[(size_t)(row + 8) * NT + col] = __floats2half2_rn(e2, e3);
            rsum[mt][0] += e0 + e1;
            rsum[mt][1] += e2 + e3;
        }
    }
#pragma unroll
    for (int off = 1; off < 4; off <<= 1)
#pragma unroll
        for (int mt = 0; mt < 4; ++mt) {
            rsum[mt][0] += __shfl_xor_sync(0xffffffffu, rsum[mt][0], off);
            rsum[mt][1] += __shfl_xor_sync(0xffffffffu, rsum[mt][1], off);
        }
    if ((lane & 3) == 0) {
#pragma unroll
        for (int mt = 0; mt < 4; ++mt) {
            int r = wm * 64 + mt * 16 + (lane >> 2);
            redsum[wn][r] = rsum[mt][0];
            redsum[wn][r + 8] = rsum[mt][1];
        }
    }
    __syncthreads();
    if (tid < 128) {
        float s = redsum[0][tid] + redsum[1][tid] + redsum[2][tid] + redsum[3][tid];
        g_psum[((size_t)bh * NT + m0 + tid) * 8 + blockIdx.x] = s;
    }
}

// ---------------------------------------------------------------------------
// 3) pv: read fp16 P, write normalized fp32 attn once, fp16 mma O = P V,
//    scale O rows by rinv in epilogue. grid (8, 96), bh reversed.
//    smem u32 words: Ps[2][2560] (fp16, row stride 20 words) at 0/2560;
//    Vs fp32 [2][64*36] at 5120 + buf*2304. Total 9728 w = 38912 B.
// ---------------------------------------------------------------------------
__global__ __launch_bounds__(256) void pv_kernel(float* __restrict__ attn)
{
    extern __shared__ uint32_t sm[];
    __shared__ float invs[128];
    const uint32_t sbase = (uint32_t)__cvta_generic_to_shared(sm);

    const int tid = threadIdx.x;
    const int lane = tid & 31;
    const int wid = tid >> 5;
    const int wm = wid >> 1, wn = wid & 1;   // warps 4x2, warp tile 32 rows x 32 d
    const int m0 = blockIdx.x * 128;
    const int bh = (NBH - 1) - blockIdx.y;

    for (int r = tid; r < 128; r += 256) {
        const float* pp = &g_psum[((size_t)bh * NT + m0 + r) * 8];
        invs[r] = 1.0f / (pp[0] + pp[1] + pp[2] + pp[3] + pp[4] + pp[5] + pp[6] + pp[7]);
    }
    __syncthreads();

    const __half* Pp = g_p + (size_t)bh * NT * NT;
    float* ap = attn + (size_t)bh * NT * NT;
    const float* V = g_v + (size_t)bh * NT * HD;

    // attn write-back mapping: 4 rows/thread, 4 cols/thread
    const int srow = tid >> 3;               // 0..31 (+u*32)
    const int sc4 = (tid & 7) * 4;           // col within 32-tile
    float myinv[4];
#pragma unroll
    for (int u = 0; u < 4; ++u) myinv[u] = invs[srow + u * 32];

    // epilogue rinv for mma rows
    float rvf[2][2];
#pragma unroll
    for (int mt = 0; mt < 2; ++mt) {
        rvf[mt][0] = invs[wm * 32 + mt * 16 + (lane >> 2)];
        rvf[mt][1] = invs[wm * 32 + mt * 16 + (lane >> 2) + 8];
    }

    const int vd = tid & 63;
    const int vk = tid >> 6;

    auto stageP = [&](int buf, int k0) {
        uint32_t pofs = sbase + (uint32_t)(buf * 2560) * 4;
#pragma unroll
        for (int u = 0; u < 2; ++u) {
            int idx = tid + u * 256;         // 0..511
            int row = idx >> 2, seg = idx & 3;
            cp16(pofs + (uint32_t)(row * 20 + seg * 4) * 4,
                 &Pp[(size_t)(m0 + row) * NT + k0 + seg * 8]);
        }
    };
    auto stageV = [&](int buf, int k0) {
        uint32_t vofs = sbase + (uint32_t)(5120 + buf * 2304) * 4;
#pragma unroll
        for (int u = 0; u < 8; ++u) {
            int k = vk + u * 4;
            cp4(vofs + (uint32_t)(vd * 36 + k) * 4, &V[(size_t)(k0 + k) * HD + vd]);
        }
    };

    stageP(0, 0);
    stageV(0, 0);
    cp_commit();

    float acc[2][4][4] = {};
    for (int kt = 0; kt < 32; ++kt) {
        const int cur = kt & 1;
        if (kt + 1 < 32) {
            stageP((kt + 1) & 1, (kt + 1) * 32);
            stageV((kt + 1) & 1, (kt + 1) * 32);
            cp_commit();
            cp_wait<1>();
        } else cp_wait<0>();
        __syncthreads();

        const uint32_t* Ps = sm + cur * 2560;
        const float* Vs = (const float*)(sm + 5120 + cur * 2304);

        // write final normalized fp32 attn from fp16 smem
#pragma unroll
        for (int u = 0; u < 4; ++u) {
            int row = srow + u * 32;
            uint2 p2 = *(const uint2*)&Ps[row * 20 + (tid & 7) * 2];
            float2 f0 = __half22float2(*(const __half2*)&p2.x);
            float2 f1 = __half22float2(*(const __half2*)&p2.y);
            float iv = myinv[u];
            float4 v = make_float4(f0.x * iv, f0.y * iv, f1.x * iv, f1.y * iv);
            __stcs((float4*)&ap[(size_t)(m0 + row) * NT + kt * 32 + sc4], v);
        }

        // fp16 mma: O += P_raw V  (2 k16 steps per 32-tile)
#pragma unroll
        for (int ks = 0; ks < 2; ++ks) {
            uint32_t a[2][4], b[4][2];
#pragma unroll
            for (int mt = 0; mt < 2; ++mt) {
                int r = wm * 32 + mt * 16 + (lane >> 2);
                int base = r * 20 + ks * 8 + (lane & 3);
                a[mt][0] = Ps[base];
                a[mt][1] = Ps[base + 160];       // row + 8
                a[mt][2] = Ps[base + 4];         // k + 8
                a[mt][3] = Ps[base + 164];
            }
#pragma unroll
            for (int nt = 0; nt < 4; ++nt) {
                int n = wn * 32 + nt * 8 + (lane >> 2);
                int kb = ks * 16 + ((lane & 3) << 1);
                b[nt][0] = h2_as_u32(__floats2half2_rn(Vs[n * 36 + kb], Vs[n * 36 + kb + 1]));
                b[nt][1] = h2_as_u32(__floats2half2_rn(Vs[n * 36 + kb + 8], Vs[n * 36 + kb + 9]));
            }
#pragma unroll
            for (int mt = 0; mt < 2; ++mt)
#pragma unroll
                for (int nt = 0; nt < 4; ++nt)
                    mma16(acc[mt][nt], a[mt][0], a[mt][1], a[mt][2], a[mt][3],
                          b[nt][0], b[nt][1]);
        }
        __syncthreads();
    }

    const int b = bh / NH, h = bh % NH;
#pragma unroll
    for (int mt = 0; mt < 2; ++mt) {
        int row = m0 + wm * 32 + mt * 16 + (lane >> 2);
#pragma unroll
        for (int nt = 0; nt < 4; ++nt) {
            int d = wn * 32 + nt * 8 + ((lane & 3) << 1);
            *(float2*)&g_x[((size_t)b * NT + row) * DIM + h * HD + d] =
                make_float2(round_tf(acc[mt][nt][0] * rvf[mt][0]),
                            round_tf(acc[mt][nt][1] * rvf[mt][0]));
            *(float2*)&g_x[((size_t)b * NT + row + 8) * DIM + h * HD + d] =
                make_float2(round_tf(acc[mt][nt][2] * rvf[mt][1]),
                            round_tf(acc[mt][nt][3] * rvf[mt][1]));
        }
    }
}

// ---------------------------------------------------------------------------
// 4) output projection, 3-stage cp.async pipeline. grid (6, 64).
// ---------------------------------------------------------------------------
__global__ __launch_bounds__(256, 2) void proj_gemm_kernel(
    const float* __restrict__ bias, float* __restrict__ out)
{
    extern __shared__ uint32_t sm[];
    const uint32_t sbase = (uint32_t)__cvta_generic_to_shared(sm);

    const float* A = g_x;
    const float* W = g_w + (size_t)3 * DIM * DIM;

    const int tid = threadIdx.x;
    const int lane = tid & 31;
    const int wid = tid >> 5;
    const int wm = wid >> 2, wn = wid & 3;
    const int m0 = blockIdx.y * 128;
    const int n0 = blockIdx.x * 128;

    const int srow = tid >> 3;
    const int skq = (tid & 7) << 2;

    auto stage = [&](int buf, int k0) {
        uint32_t aofs = sbase + (uint32_t)(buf * 4608) * 4;
        uint32_t bofs = sbase + (uint32_t)(13824 + buf * 4608) * 4;
#pragma unroll
        for (int u = 0; u < 4; ++u) {
            int row = srow + u * 32;
            cp16(aofs + (uint32_t)(row * 36 + skq) * 4, &A[(size_t)(m0 + row) * DIM + k0 + skq]);
            cp16(bofs + (uint32_t)(row * 36 + skq) * 4, &W[(size_t)(n0 + row) * DIM + k0 + skq]);
        }
        cp_commit();
    };

    float acc[4][4][4] = {};
    stage(0, 0);
    stage(1, 32);
    for (int kt = 0; kt < 24; ++kt) {
        if (kt + 2 < 24) { stage((kt + 2) % 3, (kt + 2) * 32); cp_wait<2>(); }
        else if (kt + 1 < 24) cp_wait<1>();
        else cp_wait<0>();
        __syncthreads();
        const uint32_t* As = sm + (kt % 3) * 4608;
        const uint32_t* Bs = sm + 13824 + (kt % 3) * 4608;
        compute_tiles<36, 4>(As, Bs, wm, wn, lane, acc);
        __syncthreads();
    }

#pragma unroll
    for (int mt = 0; mt < 4; ++mt) {
        int row = m0 + wm * 64 + mt * 16 + (lane >> 2);
#pragma unroll
        for (int nt = 0; nt < 4; ++nt) {
            int col = n0 + wn * 32 + nt * 8 + ((lane & 3) << 1);
            float bx = bias[col], by = bias[col + 1];
            *(float2*)&out[(size_t)row * DIM + col] =
                make_float2(acc[mt][nt][0] + bx, acc[mt][nt][1] + by);
            *(float2*)&out[(size_t)(row + 8) * DIM + col] =
                make_float2(acc[mt][nt][2] + bx, acc[mt][nt][3] + by);
        }
    }
}

// ---------------------------------------------------------------------------

extern "C" void kernel_launch(void* const* d_in, const int* in_sizes, int n_in,
                              void* d_out, int out_size)
{
    const float* tfeat = (const float*)d_in[0];
    const float* wq = (const float*)d_in[1];
    const float* bq = (const float*)d_in[2];
    const float* wk = (const float*)d_in[3];
    const float* bk = (const float*)d_in[4];
    const float* wv = (const float*)d_in[5];
    const float* bv = (const float*)d_in[6];
    const float* wp = (const float*)d_in[7];
    const float* bp = (const float*)d_in[8];

    float* xout = (float*)d_out;
    float* attn_out = (float*)d_out + (size_t)BATCH * NT * DIM;

    round_all_kernel<<<dim3(1024, 5), 256>>>(tfeat, wq, wk, wv, wp);

    cudaFuncSetAttribute(qkv_gemm_kernel, cudaFuncAttributeMaxDynamicSharedMemorySize, 110592);
    cudaFuncSetAttribute(s_exp_kernel, cudaFuncAttributeMaxDynamicSharedMemorySize, 69632);
    cudaFuncSetAttribute(pv_kernel, cudaFuncAttributeMaxDynamicSharedMemorySize, 38912);
    cudaFuncSetAttribute(proj_gemm_kernel, cudaFuncAttributeMaxDynamicSharedMemorySize, 110592);

    qkv_gemm_kernel<<<dim3(DIM / 128, (BATCH * NT) / 128, 3), 256, 110592>>>(bq, bk, bv);
    s_exp_kernel<<<dim3(NT / 128, NT / 128, NBH), 256, 69632>>>();
    pv_kernel<<<dim3(NT / 128, NBH), 256, 38912>>>(attn_out);
    proj_gemm_kernel<<<dim3(DIM / 128, (BATCH * NT) / 128), 256, 110592>>>(bp, xout);
}

// round 12
// speedup vs baseline: 1.2100x; 1.1498x over previous
#include <cuda_runtime.h>
#include <cuda_fp16.h>
#include <cstdint>

#define BATCH 8
#define NT 1024
#define DIM 768
#define NH 12
#define HD 64
#define SCALE 0.125f
#define NBH (BATCH * NH)

// scratch (allocation-free rule: __device__ globals)
__device__ __half g_qh[NBH * NT * HD];                // Q fp16 [bh][t][d]
__device__ __half g_kh[NBH * NT * HD];                // K fp16 [bh][t][d]
__device__ __half g_vt[NBH * HD * NT];                // V fp16 transposed [bh][d][t]
__device__ float g_x[BATCH * NT * DIM];
__device__ float g_tf[BATCH * NT * DIM];              // tf32-rounded tfeat
__device__ float g_w[4 * DIM * DIM];                  // tf32-rounded weights
__device__ float g_psum[(size_t)NBH * NT * 8];
__device__ __half g_p[(size_t)NBH * NT * NT];         // unnormalized exp scores, fp16

// ---------------------------------------------------------------------------
// helpers
// ---------------------------------------------------------------------------
__device__ __forceinline__ uint32_t f2tf(float x) {
    uint32_t r;
    asm("cvt.rna.tf32.f32 %0, %1;" : "=r"(r) : "f"(x));
    return r;
}
__device__ __forceinline__ float round_tf(float x) { return __uint_as_float(f2tf(x)); }

__device__ __forceinline__ uint32_t h2_as_u32(__half2 h) {
    union { __half2 h2; uint32_t u; } cvt;
    cvt.h2 = h;
    return cvt.u;
}

__device__ __forceinline__ void cp16(uint32_t s, const void* g) {
    asm volatile("cp.async.cg.shared.global [%0], [%1], 16;" :: "r"(s), "l"(g));
}
__device__ __forceinline__ void cp_commit() { asm volatile("cp.async.commit_group;"); }
template <int N> __device__ __forceinline__ void cp_wait() {
    asm volatile("cp.async.wait_group %0;" :: "n"(N));
}

__device__ __forceinline__ void mma8(float* c,
                                     uint32_t a0, uint32_t a1, uint32_t a2, uint32_t a3,
                                     uint32_t b0, uint32_t b1) {
    asm volatile(
        "mma.sync.aligned.m16n8k8.row.col.f32.tf32.tf32.f32 "
        "{%0,%1,%2,%3},{%4,%5,%6,%7},{%8,%9},{%0,%1,%2,%3};"
        : "+f"(c[0]), "+f"(c[1]), "+f"(c[2]), "+f"(c[3])
        : "r"(a0), "r"(a1), "r"(a2), "r"(a3), "r"(b0), "r"(b1));
}

__device__ __forceinline__ void mma16(float* c,
                                      uint32_t a0, uint32_t a1, uint32_t a2, uint32_t a3,
                                      uint32_t b0, uint32_t b1) {
    asm volatile(
        "mma.sync.aligned.m16n8k16.row.col.f32.f16.f16.f32 "
        "{%0,%1,%2,%3},{%4,%5,%6,%7},{%8,%9},{%0,%1,%2,%3};"
        : "+f"(c[0]), "+f"(c[1]), "+f"(c[2]), "+f"(c[3])
        : "r"(a0), "r"(a1), "r"(a2), "r"(a3), "r"(b0), "r"(b1));
}

// tf32 128x128 block, 8 warps as 2x4 (warp tile 64x32)
template <int STRIDE, int NKS>
__device__ __forceinline__ void compute_tiles(const uint32_t* __restrict__ As,
                                              const uint32_t* __restrict__ Bs,
                                              int wm, int wn, int lane,
                                              float acc[4][4][4]) {
#pragma unroll
    for (int ks = 0; ks < NKS; ++ks) {
        const int col = ks * 8 + (lane & 3);
        uint32_t a[4][4], b[4][2];
#pragma unroll
        for (int mt = 0; mt < 4; ++mt) {
            int r = wm * 64 + mt * 16 + (lane >> 2);
            a[mt][0] = As[r * STRIDE + col];
            a[mt][1] = As[(r + 8) * STRIDE + col];
            a[mt][2] = As[r * STRIDE + col + 4];
            a[mt][3] = As[(r + 8) * STRIDE + col + 4];
        }
#pragma unroll
        for (int nt = 0; nt < 4; ++nt) {
            int n = wn * 32 + nt * 8 + (lane >> 2);
            b[nt][0] = Bs[n * STRIDE + col];
            b[nt][1] = Bs[n * STRIDE + col + 4];
        }
#pragma unroll
        for (int mt = 0; mt < 4; ++mt)
#pragma unroll
            for (int nt = 0; nt < 4; ++nt)
                mma8(acc[mt][nt], a[mt][0], a[mt][1], a[mt][2], a[mt][3],
                     b[nt][0], b[nt][1]);
    }
}

// fp16 128x128 block, K=64 (4 k16 steps), operands at word-stride STRIDE
template <int STRIDE>
__device__ __forceinline__ void compute_tiles16(const uint32_t* __restrict__ As,
                                                const uint32_t* __restrict__ Bs,
                                                int wm, int wn, int lane,
                                                float acc[4][4][4]) {
#pragma unroll
    for (int ks = 0; ks < 4; ++ks) {
        const int col = ks * 8 + (lane & 3);
        uint32_t a[4][4], b[4][2];
#pragma unroll
        for (int mt = 0; mt < 4; ++mt) {
            int r = wm * 64 + mt * 16 + (lane >> 2);
            a[mt][0] = As[r * STRIDE + col];
            a[mt][1] = As[(r + 8) * STRIDE + col];
            a[mt][2] = As[r * STRIDE + col + 4];
            a[mt][3] = As[(r + 8) * STRIDE + col + 4];
        }
#pragma unroll
        for (int nt = 0; nt < 4; ++nt) {
            int n = wn * 32 + nt * 8 + (lane >> 2);
            b[nt][0] = Bs[n * STRIDE + col];
            b[nt][1] = Bs[n * STRIDE + col + 4];
        }
#pragma unroll
        for (int mt = 0; mt < 4; ++mt)
#pragma unroll
            for (int nt = 0; nt < 4; ++nt)
                mma16(acc[mt][nt], a[mt][0], a[mt][1], a[mt][2], a[mt][3],
                      b[nt][0], b[nt][1]);
    }
}

// ---------------------------------------------------------------------------
// 0) tf32 pre-rounding, one launch
// ---------------------------------------------------------------------------
__global__ void round_all_kernel(const float* __restrict__ tfeat,
                                 const float* __restrict__ wq,
                                 const float* __restrict__ wk,
                                 const float* __restrict__ wv,
                                 const float* __restrict__ wp) {
    const int y = blockIdx.y;
    const float* src;
    float* dst;
    int n4;
    if (y == 0) { src = tfeat; dst = g_tf; n4 = BATCH * NT * DIM / 4; }
    else {
        src = (y == 1) ? wq : (y == 2) ? wk : (y == 3) ? wv : wp;
        dst = g_w + (size_t)(y - 1) * DIM * DIM;
        n4 = DIM * DIM / 4;
    }
    for (int i = blockIdx.x * blockDim.x + threadIdx.x; i < n4;
         i += gridDim.x * blockDim.x) {
        float4 v = ((const float4*)src)[i];
        v.x = round_tf(v.x); v.y = round_tf(v.y);
        v.z = round_tf(v.z); v.w = round_tf(v.w);
        ((float4*)dst)[i] = v;
    }
}

// ---------------------------------------------------------------------------
// 1) QKV projection, 3-stage cp.async pipeline. grid (6, 64, 3).
//    Q/K epilogue -> fp16 [bh][t][d]; V epilogue -> fp16 transposed [bh][d][t].
// ---------------------------------------------------------------------------
__global__ __launch_bounds__(256, 2) void qkv_gemm_kernel(
    const float* __restrict__ bq, const float* __restrict__ bk,
    const float* __restrict__ bv)
{
    extern __shared__ uint32_t sm[];
    const uint32_t sbase = (uint32_t)__cvta_generic_to_shared(sm);

    const int z = blockIdx.z;
    const float* A = g_tf;
    const float* W = g_w + (size_t)z * DIM * DIM;
    const float* bias = (z == 0) ? bq : (z == 1) ? bk : bv;

    const int tid = threadIdx.x;
    const int lane = tid & 31;
    const int wid = tid >> 5;
    const int wm = wid >> 2, wn = wid & 3;
    const int m0 = blockIdx.y * 128;
    const int n0 = blockIdx.x * 128;

    const int srow = tid >> 3;
    const int skq = (tid & 7) << 2;

    auto stage = [&](int buf, int k0) {
        uint32_t aofs = sbase + (uint32_t)(buf * 4608) * 4;
        uint32_t bofs = sbase + (uint32_t)(13824 + buf * 4608) * 4;
#pragma unroll
        for (int u = 0; u < 4; ++u) {
            int row = srow + u * 32;
            cp16(aofs + (uint32_t)(row * 36 + skq) * 4, &A[(size_t)(m0 + row) * DIM + k0 + skq]);
            cp16(bofs + (uint32_t)(row * 36 + skq) * 4, &W[(size_t)(n0 + row) * DIM + k0 + skq]);
        }
        cp_commit();
    };

    float acc[4][4][4] = {};
    stage(0, 0);
    stage(1, 32);
    for (int kt = 0; kt < 24; ++kt) {
        if (kt + 2 < 24) { stage((kt + 2) % 3, (kt + 2) * 32); cp_wait<2>(); }
        else if (kt + 1 < 24) cp_wait<1>();
        else cp_wait<0>();
        __syncthreads();
        const uint32_t* As = sm + (kt % 3) * 4608;
        const uint32_t* Bs = sm + 13824 + (kt % 3) * 4608;
        compute_tiles<36, 4>(As, Bs, wm, wn, lane, acc);
        __syncthreads();
    }

    if (z < 2) {
        __half* out = (z == 0) ? g_qh : g_kh;
#pragma unroll
        for (int mt = 0; mt < 4; ++mt) {
            int row = m0 + wm * 64 + mt * 16 + (lane >> 2);
            int b0i = row >> 10, t0 = row & 1023;
#pragma unroll
            for (int nt = 0; nt < 4; ++nt) {
                int col = n0 + wn * 32 + nt * 8 + ((lane & 3) << 1);
                int h = col >> 6, d = col & 63;
                float bx = bias[col], by = bias[col + 1];
                *(uint32_t*)&out[((size_t)(b0i * NH + h) * NT + t0) * HD + d] =
                    h2_as_u32(__floats2half2_rn(acc[mt][nt][0] + bx, acc[mt][nt][1] + by));
                *(uint32_t*)&out[((size_t)(b0i * NH + h) * NT + t0 + 8) * HD + d] =
                    h2_as_u32(__floats2half2_rn(acc[mt][nt][2] + bx, acc[mt][nt][3] + by));
            }
        }
    } else {
        // transpose through smem: T[t_local][d_local], stride 133 (fp32)
        __syncthreads();
        float* T = (float*)sm;
#pragma unroll
        for (int mt = 0; mt < 4; ++mt) {
            int lr = wm * 64 + mt * 16 + (lane >> 2);
#pragma unroll
            for (int nt = 0; nt < 4; ++nt) {
                int lc = wn * 32 + nt * 8 + ((lane & 3) << 1);
                float bx = bias[n0 + lc], by = bias[n0 + lc + 1];
                T[lr * 133 + lc]           = acc[mt][nt][0] + bx;
                T[lr * 133 + lc + 1]       = acc[mt][nt][1] + by;
                T[(lr + 8) * 133 + lc]     = acc[mt][nt][2] + bx;
                T[(lr + 8) * 133 + lc + 1] = acc[mt][nt][3] + by;
            }
        }
        __syncthreads();
        const int b0i = m0 >> 10;
        const int t00 = m0 & 1023;
#pragma unroll
        for (int u = 0; u < 16; ++u) {
            int idx = tid + u * 256;
            int dcol = idx >> 5;
            int tq = (idx & 31) << 2;
            uint2 v;
            v.x = h2_as_u32(__floats2half2_rn(T[(tq + 0) * 133 + dcol], T[(tq + 1) * 133 + dcol]));
            v.y = h2_as_u32(__floats2half2_rn(T[(tq + 2) * 133 + dcol], T[(tq + 3) * 133 + dcol]));
            int h = (n0 + dcol) >> 6, d = (n0 + dcol) & 63;
            *(uint2*)&g_vt[((size_t)(b0i * NH + h) * HD + d) * NT + t00 + tq] = v;
        }
    }
}

// ---------------------------------------------------------------------------
// 2) S: fp16 mma exp(Q K^T * SCALE) -> fp16 g_p + row-sum partials.
//    grid (8, 8, 96). smem: Qh/Kh tiles 128 x 36 words each -> 36864 B.
// ---------------------------------------------------------------------------
__global__ __launch_bounds__(256) void s_exp_kernel()
{
    extern __shared__ uint32_t sm[];
    __shared__ float redsum[4][128];
    const uint32_t sbase = (uint32_t)__cvta_generic_to_shared(sm);

    const int tid = threadIdx.x;
    const int lane = tid & 31;
    const int wid = tid >> 5;
    const int wm = wid >> 2, wn = wid & 3;
    const int bh = blockIdx.z;
    const int m0 = blockIdx.y * 128;
    const int n0 = blockIdx.x * 128;

    const __half* Q = g_qh + (size_t)bh * NT * HD;
    const __half* K = g_kh + (size_t)bh * NT * HD;

    {
        const uint32_t kofs = sbase + (uint32_t)4608 * 4;
#pragma unroll
        for (int u = 0; u < 4; ++u) {
            int idx = tid + u * 256;
            int row = idx >> 3;
            int seg = idx & 7;                 // 8 halves per cp16
            cp16(sbase + (uint32_t)(row * 36 + seg * 4) * 4, &Q[(size_t)(m0 + row) * HD + seg * 8]);
            cp16(kofs + (uint32_t)(row * 36 + seg * 4) * 4, &K[(size_t)(n0 + row) * HD + seg * 8]);
        }
        cp_commit();
        cp_wait<0>();
        __syncthreads();
    }

    float acc[4][4][4] = {};
    compute_tiles16<36>(sm, sm + 4608, wm, wn, lane, acc);

    float rsum[4][2] = {};
    __half* pp = g_p + (size_t)bh * NT * NT;
#pragma unroll
    for (int mt = 0; mt < 4; ++mt) {
        int row = m0 + wm * 64 + mt * 16 + (lane >> 2);
#pragma unroll
        for (int nt = 0; nt < 4; ++nt) {
            int col = n0 + wn * 32 + nt * 8 + ((lane & 3) << 1);
            float e0 = __expf(acc[mt][nt][0] * SCALE);
            float e1 = __expf(acc[mt][nt][1] * SCALE);
            float e2 = __expf(acc[mt][nt][2] * SCALE);
            float e3 = __expf(acc[mt][nt][3] * SCALE);
            *(__half2*)&pp[(size_t)row * NT + col] = __floats2half2_rn(e0, e1);
            *(__half2*)&pp[(size_t)(row + 8) * NT + col] = __floats2half2_rn(e2, e3);
            rsum[mt][0] += e0 + e1;
            rsum[mt][1] += e2 + e3;
        }
    }
#pragma unroll
    for (int off = 1; off < 4; off <<= 1)
#pragma unroll
        for (int mt = 0; mt < 4; ++mt) {
            rsum[mt][0] += __shfl_xor_sync(0xffffffffu, rsum[mt][0], off);
            rsum[mt][1] += __shfl_xor_sync(0xffffffffu, rsum[mt][1], off);
        }
    if ((lane & 3) == 0) {
#pragma unroll
        for (int mt = 0; mt < 4; ++mt) {
            int r = wm * 64 + mt * 16 + (lane >> 2);
            redsum[wn][r] = rsum[mt][0];
            redsum[wn][r + 8] = rsum[mt][1];
        }
    }
    __syncthreads();
    if (tid < 128) {
        float s = redsum[0][tid] + redsum[1][tid] + redsum[2][tid] + redsum[3][tid];
        g_psum[((size_t)bh * NT + m0 + tid) * 8 + blockIdx.x] = s;
    }
}

// ---------------------------------------------------------------------------
// 3) pv: fp16 P + fp16 V(transposed), fp32 attn write, epilogue rinv scaling.
//    grid (8, 96), bh reversed. smem words:
//    Ps[2][2560] (stride 20 w/row) at 0/2560; Vt[2][64*20] at 5120 + buf*1280.
//    Total 7680 w = 30720 B.
// ---------------------------------------------------------------------------
__global__ __launch_bounds__(256) void pv_kernel(float* __restrict__ attn)
{
    extern __shared__ uint32_t sm[];
    __shared__ float invs[128];
    const uint32_t sbase = (uint32_t)__cvta_generic_to_shared(sm);

    const int tid = threadIdx.x;
    const int lane = tid & 31;
    const int wid = tid >> 5;
    const int wm = wid >> 1, wn = wid & 1;   // warps 4x2, warp tile 32 rows x 32 d
    const int m0 = blockIdx.x * 128;
    const int bh = (NBH - 1) - blockIdx.y;

    for (int r = tid; r < 128; r += 256) {
        const float* pp = &g_psum[((size_t)bh * NT + m0 + r) * 8];
        invs[r] = 1.0f / (pp[0] + pp[1] + pp[2] + pp[3] + pp[4] + pp[5] + pp[6] + pp[7]);
    }
    __syncthreads();

    const __half* Pp = g_p + (size_t)bh * NT * NT;
    float* ap = attn + (size_t)bh * NT * NT;
    const __half* VT = g_vt + (size_t)bh * HD * NT;

    const int srow = tid >> 3;               // 0..31 (+u*32)
    const int sc4 = (tid & 7) * 4;           // col within 32-tile
    float myinv[4];
#pragma unroll
    for (int u = 0; u < 4; ++u) myinv[u] = invs[srow + u * 32];

    float rvf[2][2];
#pragma unroll
    for (int mt = 0; mt < 2; ++mt) {
        rvf[mt][0] = invs[wm * 32 + mt * 16 + (lane >> 2)];
        rvf[mt][1] = invs[wm * 32 + mt * 16 + (lane >> 2) + 8];
    }

    auto stageP = [&](int buf, int k0) {
        uint32_t pofs = sbase + (uint32_t)(buf * 2560) * 4;
#pragma unroll
        for (int u = 0; u < 2; ++u) {
            int idx = tid + u * 256;         // 0..511
            int row = idx >> 2, seg = idx & 3;
            cp16(pofs + (uint32_t)(row * 20 + seg * 4) * 4,
                 &Pp[(size_t)(m0 + row) * NT + k0 + seg * 8]);
        }
    };
    auto stageV = [&](int buf, int k0) {
        uint32_t vofs = sbase + (uint32_t)(5120 + buf * 1280) * 4;
        int d = tid >> 2, seg = tid & 3;     // 64 d-rows x 4 cp16 (32 halves/row)
        cp16(vofs + (uint32_t)(d * 20 + seg * 4) * 4,
             &VT[(size_t)d * NT + k0 + seg * 8]);
    };

    stageP(0, 0);
    stageV(0, 0);
    cp_commit();

    float acc[2][4][4] = {};
    for (int kt = 0; kt < 32; ++kt) {
        const int cur = kt & 1;
        if (kt + 1 < 32) {
            stageP((kt + 1) & 1, (kt + 1) * 32);
            stageV((kt + 1) & 1, (kt + 1) * 32);
            cp_commit();
            cp_wait<1>();
        } else cp_wait<0>();
        __syncthreads();

        const uint32_t* Ps = sm + cur * 2560;
        const uint32_t* Vs = sm + 5120 + cur * 1280;

        // write final normalized fp32 attn from fp16 smem
#pragma unroll
        for (int u = 0; u < 4; ++u) {
            int row = srow + u * 32;
            uint2 p2 = *(const uint2*)&Ps[row * 20 + (tid & 7) * 2];
            float2 f0 = __half22float2(*(const __half2*)&p2.x);
            float2 f1 = __half22float2(*(const __half2*)&p2.y);
            float iv = myinv[u];
            float4 v = make_float4(f0.x * iv, f0.y * iv, f1.x * iv, f1.y * iv);
            __stcs((float4*)&ap[(size_t)(m0 + row) * NT + kt * 32 + sc4], v);
        }

        // fp16 mma: O += P_raw V  (2 k16 steps per 32-tile)
#pragma unroll
        for (int ks = 0; ks < 2; ++ks) {
            uint32_t a[2][4], b[4][2];
#pragma unroll
            for (int mt = 0; mt < 2; ++mt) {
                int r = wm * 32 + mt * 16 + (lane >> 2);
                int base = r * 20 + ks * 8 + (lane & 3);
                a[mt][0] = Ps[base];
                a[mt][1] = Ps[base + 160];       // row + 8
                a[mt][2] = Ps[base + 4];         // k + 8
                a[mt][3] = Ps[base + 164];
            }
#pragma unroll
            for (int nt = 0; nt < 4; ++nt) {
                int n = wn * 32 + nt * 8 + (lane >> 2);
                int base = n * 20 + ks * 8 + (lane & 3);
                b[nt][0] = Vs[base];
                b[nt][1] = Vs[base + 4];
            }
#pragma unroll
            for (int mt = 0; mt < 2; ++mt)
#pragma unroll
                for (int nt = 0; nt < 4; ++nt)
                    mma16(acc[mt][nt], a[mt][0], a[mt][1], a[mt][2], a[mt][3],
                          b[nt][0], b[nt][1]);
        }
        __syncthreads();
    }

    const int b = bh / NH, h = bh % NH;
#pragma unroll
    for (int mt = 0; mt < 2; ++mt) {
        int row = m0 + wm * 32 + mt * 16 + (lane >> 2);
#pragma unroll
        for (int nt = 0; nt < 4; ++nt) {
            int d = wn * 32 + nt * 8 + ((lane & 3) << 1);
            *(float2*)&g_x[((size_t)b * NT + row) * DIM + h * HD + d] =
                make_float2(round_tf(acc[mt][nt][0] * rvf[mt][0]),
                            round_tf(acc[mt][nt][1] * rvf[mt][0]));
            *(float2*)&g_x[((size_t)b * NT + row + 8) * DIM + h * HD + d] =
                make_float2(round_tf(acc[mt][nt][2] * rvf[mt][1]),
                            round_tf(acc[mt][nt][3] * rvf[mt][1]));
        }
    }
}

// ---------------------------------------------------------------------------
// 4) output projection, 3-stage cp.async pipeline. grid (6, 64).
// ---------------------------------------------------------------------------
__global__ __launch_bounds__(256, 2) void proj_gemm_kernel(
    const float* __restrict__ bias, float* __restrict__ out)
{
    extern __shared__ uint32_t sm[];
    const uint32_t sbase = (uint32_t)__cvta_generic_to_shared(sm);

    const float* A = g_x;
    const float* W = g_w + (size_t)3 * DIM * DIM;

    const int tid = threadIdx.x;
    const int lane = tid & 31;
    const int wid = tid >> 5;
    const int wm = wid >> 2, wn = wid & 3;
    const int m0 = blockIdx.y * 128;
    const int n0 = blockIdx.x * 128;

    const int srow = tid >> 3;
    const int skq = (tid & 7) << 2;

    auto stage = [&](int buf, int k0) {
        uint32_t aofs = sbase + (uint32_t)(buf * 4608) * 4;
        uint32_t bofs = sbase + (uint32_t)(13824 + buf * 4608) * 4;
#pragma unroll
        for (int u = 0; u < 4; ++u) {
            int row = srow + u * 32;
            cp16(aofs + (uint32_t)(row * 36 + skq) * 4, &A[(size_t)(m0 + row) * DIM + k0 + skq]);
            cp16(bofs + (uint32_t)(row * 36 + skq) * 4, &W[(size_t)(n0 + row) * DIM + k0 + skq]);
        }
        cp_commit();
    };

    float acc[4][4][4] = {};
    stage(0, 0);
    stage(1, 32);
    for (int kt = 0; kt < 24; ++kt) {
        if (kt + 2 < 24) { stage((kt + 2) % 3, (kt + 2) * 32); cp_wait<2>(); }
        else if (kt + 1 < 24) cp_wait<1>();
        else cp_wait<0>();
        __syncthreads();
        const uint32_t* As = sm + (kt % 3) * 4608;
        const uint32_t* Bs = sm + 13824 + (kt % 3) * 4608;
        compute_tiles<36, 4>(As, Bs, wm, wn, lane, acc);
        __syncthreads();
    }

#pragma unroll
    for (int mt = 0; mt < 4; ++mt) {
        int row = m0 + wm * 64 + mt * 16 + (lane >> 2);
#pragma unroll
        for (int nt = 0; nt < 4; ++nt) {
            int col = n0 + wn * 32 + nt * 8 + ((lane & 3) << 1);
            float bx = bias[col], by = bias[col + 1];
            *(float2*)&out[(size_t)row * DIM + col] =
                make_float2(acc[mt][nt][0] + bx, acc[mt][nt][1] + by);
            *(float2*)&out[(size_t)(row + 8) * DIM + col] =
                make_float2(acc[mt][nt][2] + bx, acc[mt][nt][3] + by);
        }
    }
}

// ---------------------------------------------------------------------------

extern "C" void kernel_launch(void* const* d_in, const int* in_sizes, int n_in,
                              void* d_out, int out_size)
{
    const float* tfeat = (const float*)d_in[0];
    const float* wq = (const float*)d_in[1];
    const float* bq = (const float*)d_in[2];
    const float* wk = (const float*)d_in[3];
    const float* bk = (const float*)d_in[4];
    const float* wv = (const float*)d_in[5];
    const float* bv = (const float*)d_in[6];
    const float* wp = (const float*)d_in[7];
    const float* bp = (const float*)d_in[8];

    float* xout = (float*)d_out;
    float* attn_out = (float*)d_out + (size_t)BATCH * NT * DIM;

    round_all_kernel<<<dim3(1024, 5), 256>>>(tfeat, wq, wk, wv, wp);

    cudaFuncSetAttribute(qkv_gemm_kernel, cudaFuncAttributeMaxDynamicSharedMemorySize, 110592);
    cudaFuncSetAttribute(s_exp_kernel, cudaFuncAttributeMaxDynamicSharedMemorySize, 36864);
    cudaFuncSetAttribute(pv_kernel, cudaFuncAttributeMaxDynamicSharedMemorySize, 30720);
    cudaFuncSetAttribute(proj_gemm_kernel, cudaFuncAttributeMaxDynamicSharedMemorySize, 110592);

    qkv_gemm_kernel<<<dim3(DIM / 128, (BATCH * NT) / 128, 3), 256, 110592>>>(bq, bk, bv);
    s_exp_kernel<<<dim3(NT / 128, NT / 128, NBH), 256, 36864>>>();
    pv_kernel<<<dim3(NT / 128, NBH), 256, 30720>>>(attn_out);
    proj_gemm_kernel<<<dim3(DIM / 128, (BATCH * NT) / 128), 256, 110592>>>(bp, xout);
}

// round 14
// speedup vs baseline: 1.5963x; 1.3192x over previous
#include <cuda_runtime.h>
#include <cuda_fp16.h>
#include <cstdint>

#define BATCH 8
#define NT 1024
#define DIM 768
#define NH 12
#define HD 64
#define SCALE 0.125f
#define NBH (BATCH * NH)

// scratch (allocation-free rule: __device__ globals)
__device__ __half g_qh[NBH * NT * HD];                // Q fp16 [bh][t][d]
__device__ __half g_kh[NBH * NT * HD];                // K fp16 [bh][t][d]
__device__ __half g_vt[NBH * HD * NT];                // V fp16 transposed [bh][d][t]
__device__ __half g_xh[BATCH * NT * DIM];             // attention output, fp16
__device__ __half g_tfh[BATCH * NT * DIM];            // fp16 tfeat
__device__ __half g_wh[4 * DIM * DIM];                // fp16 wq,wk,wv,wp
__device__ float g_psum[(size_t)NBH * NT * 8];
__device__ __half g_p[(size_t)NBH * NT * NT];         // unnormalized exp scores, fp16

// ---------------------------------------------------------------------------
// helpers
// ---------------------------------------------------------------------------
__device__ __forceinline__ uint32_t h2_as_u32(__half2 h) {
    union { __half2 h2; uint32_t u; } cvt;
    cvt.h2 = h;
    return cvt.u;
}

__device__ __forceinline__ void cp16(uint32_t s, const void* g) {
    asm volatile("cp.async.cg.shared.global [%0], [%1], 16;" :: "r"(s), "l"(g));
}
__device__ __forceinline__ void cp_commit() { asm volatile("cp.async.commit_group;"); }
template <int N> __device__ __forceinline__ void cp_wait() {
    asm volatile("cp.async.wait_group %0;" :: "n"(N));
}

__device__ __forceinline__ void mma16(float* c,
                                      uint32_t a0, uint32_t a1, uint32_t a2, uint32_t a3,
                                      uint32_t b0, uint32_t b1) {
    asm volatile(
        "mma.sync.aligned.m16n8k16.row.col.f32.f16.f16.f32 "
        "{%0,%1,%2,%3},{%4,%5,%6,%7},{%8,%9},{%0,%1,%2,%3};"
        : "+f"(c[0]), "+f"(c[1]), "+f"(c[2]), "+f"(c[3])
        : "r"(a0), "r"(a1), "r"(a2), "r"(a3), "r"(b0), "r"(b1));
}

// fp16 128x128 block, K=64 (4 k16 steps), operands at word-stride STRIDE
// (rows hold 64 halves = 32 words + 4 pad). 8 warps as 2x4 (warp tile 64x32).
template <int STRIDE>
__device__ __forceinline__ void compute_tiles16(const uint32_t* __restrict__ As,
                                                const uint32_t* __restrict__ Bs,
                                                int wm, int wn, int lane,
                                                float acc[4][4][4]) {
#pragma unroll
    for (int ks = 0; ks < 4; ++ks) {
        const int col = ks * 8 + (lane & 3);
        uint32_t a[4][4], b[4][2];
#pragma unroll
        for (int mt = 0; mt < 4; ++mt) {
            int r = wm * 64 + mt * 16 + (lane >> 2);
            a[mt][0] = As[r * STRIDE + col];
            a[mt][1] = As[(r + 8) * STRIDE + col];
            a[mt][2] = As[r * STRIDE + col + 4];
            a[mt][3] = As[(r + 8) * STRIDE + col + 4];
        }
#pragma unroll
        for (int nt = 0; nt < 4; ++nt) {
            int n = wn * 32 + nt * 8 + (lane >> 2);
            b[nt][0] = Bs[n * STRIDE + col];
            b[nt][1] = Bs[n * STRIDE + col + 4];
        }
#pragma unroll
        for (int mt = 0; mt < 4; ++mt)
#pragma unroll
            for (int nt = 0; nt < 4; ++nt)
                mma16(acc[mt][nt], a[mt][0], a[mt][1], a[mt][2], a[mt][3],
                      b[nt][0], b[nt][1]);
    }
}

// ---------------------------------------------------------------------------
// 0) fp16 pre-rounding, one launch
// ---------------------------------------------------------------------------
__global__ void round_all_kernel(const float* __restrict__ tfeat,
                                 const float* __restrict__ wq,
                                 const float* __restrict__ wk,
                                 const float* __restrict__ wv,
                                 const float* __restrict__ wp) {
    const int y = blockIdx.y;
    const float* src;
    __half* dst;
    int n4;
    if (y == 0) { src = tfeat; dst = g_tfh; n4 = BATCH * NT * DIM / 4; }
    else {
        src = (y == 1) ? wq : (y == 2) ? wk : (y == 3) ? wv : wp;
        dst = g_wh + (size_t)(y - 1) * DIM * DIM;
        n4 = DIM * DIM / 4;
    }
    for (int i = blockIdx.x * blockDim.x + threadIdx.x; i < n4;
         i += gridDim.x * blockDim.x) {
        float4 v = ((const float4*)src)[i];
        uint2 o;
        o.x = h2_as_u32(__floats2half2_rn(v.x, v.y));
        o.y = h2_as_u32(__floats2half2_rn(v.z, v.w));
        ((uint2*)dst)[i] = o;
    }
}

// stage a 128-row x 64-half tile (stride 36 words) -- 8 cp16s per row
__device__ __forceinline__ void stage_tile_h(uint32_t dst_base, const __half* src,
                                             int row0, int ld, int k0, int tid) {
#pragma unroll
    for (int u = 0; u < 4; ++u) {
        int idx = tid + u * 256;         // 0..1023
        int row = idx >> 3;              // 0..127
        int seg = idx & 7;               // 0..7, 8 halves each
        cp16(dst_base + (uint32_t)(row * 36 + seg * 4) * 4,
             &src[(size_t)(row0 + row) * ld + k0 + seg * 8]);
    }
}

// ---------------------------------------------------------------------------
// 1) QKV projection, fp16 mma, 3-stage cp.async (K=64/stage). grid (6, 64, 3).
//    smem: A 3x4608 w at 0, B 3x4608 w at 13824 -> 110592 B.
// ---------------------------------------------------------------------------
__global__ __launch_bounds__(256, 2) void qkv_gemm_kernel(
    const float* __restrict__ bq, const float* __restrict__ bk,
    const float* __restrict__ bv)
{
    extern __shared__ uint32_t sm[];
    const uint32_t sbase = (uint32_t)__cvta_generic_to_shared(sm);

    const int z = blockIdx.z;
    const __half* A = g_tfh;
    const __half* W = g_wh + (size_t)z * DIM * DIM;
    const float* bias = (z == 0) ? bq : (z == 1) ? bk : bv;

    const int tid = threadIdx.x;
    const int lane = tid & 31;
    const int wid = tid >> 5;
    const int wm = wid >> 2, wn = wid & 3;
    const int m0 = blockIdx.y * 128;
    const int n0 = blockIdx.x * 128;

    auto stage = [&](int buf, int k0) {
        stage_tile_h(sbase + (uint32_t)(buf * 4608) * 4, A, m0, DIM, k0, tid);
        stage_tile_h(sbase + (uint32_t)(13824 + buf * 4608) * 4, W, n0, DIM, k0, tid);
        cp_commit();
    };

    float acc[4][4][4] = {};
    stage(0, 0);
    stage(1, 64);
    for (int kt = 0; kt < 12; ++kt) {
        if (kt + 2 < 12) { stage((kt + 2) % 3, (kt + 2) * 64); cp_wait<2>(); }
        else if (kt + 1 < 12) cp_wait<1>();
        else cp_wait<0>();
        __syncthreads();
        compute_tiles16<36>(sm + (kt % 3) * 4608, sm + 13824 + (kt % 3) * 4608,
                            wm, wn, lane, acc);
        __syncthreads();
    }

    if (z < 2) {
        __half* out = (z == 0) ? g_qh : g_kh;
#pragma unroll
        for (int mt = 0; mt < 4; ++mt) {
            int row = m0 + wm * 64 + mt * 16 + (lane >> 2);
            int b0i = row >> 10, t0 = row & 1023;
#pragma unroll
            for (int nt = 0; nt < 4; ++nt) {
                int col = n0 + wn * 32 + nt * 8 + ((lane & 3) << 1);
                int h = col >> 6, d = col & 63;
                float bx = bias[col], by = bias[col + 1];
                *(uint32_t*)&out[((size_t)(b0i * NH + h) * NT + t0) * HD + d] =
                    h2_as_u32(__floats2half2_rn(acc[mt][nt][0] + bx, acc[mt][nt][1] + by));
                *(uint32_t*)&out[((size_t)(b0i * NH + h) * NT + t0 + 8) * HD + d] =
                    h2_as_u32(__floats2half2_rn(acc[mt][nt][2] + bx, acc[mt][nt][3] + by));
            }
        }
    } else {
        // transpose through smem: T[t_local][d_local], stride 133 (fp32)
        __syncthreads();
        float* T = (float*)sm;
#pragma unroll
        for (int mt = 0; mt < 4; ++mt) {
            int lr = wm * 64 + mt * 16 + (lane >> 2);
#pragma unroll
            for (int nt = 0; nt < 4; ++nt) {
                int lc = wn * 32 + nt * 8 + ((lane & 3) << 1);
                float bx = bias[n0 + lc], by = bias[n0 + lc + 1];
                T[lr * 133 + lc]           = acc[mt][nt][0] + bx;
                T[lr * 133 + lc + 1]       = acc[mt][nt][1] + by;
                T[(lr + 8) * 133 + lc]     = acc[mt][nt][2] + bx;
                T[(lr + 8) * 133 + lc + 1] = acc[mt][nt][3] + by;
            }
        }
        __syncthreads();
        const int b0i = m0 >> 10;
        const int t00 = m0 & 1023;
#pragma unroll
        for (int u = 0; u < 16; ++u) {
            int idx = tid + u * 256;
            int dcol = idx >> 5;
            int tq = (idx & 31) << 2;
            uint2 v;
            v.x = h2_as_u32(__floats2half2_rn(T[(tq + 0) * 133 + dcol], T[(tq + 1) * 133 + dcol]));
            v.y = h2_as_u32(__floats2half2_rn(T[(tq + 2) * 133 + dcol], T[(tq + 3) * 133 + dcol]));
            int h = (n0 + dcol) >> 6, d = (n0 + dcol) & 63;
            *(uint2*)&g_vt[((size_t)(b0i * NH + h) * HD + d) * NT + t00 + tq] = v;
        }
    }
}

// ---------------------------------------------------------------------------
// 2) S: fp16 mma exp(Q K^T * SCALE) -> fp16 g_p + row-sum partials.
//    grid (8, 8, 96). smem: Qh/Kh tiles 128 x 36 words each -> 36864 B.
// ---------------------------------------------------------------------------
__global__ __launch_bounds__(256) void s_exp_kernel()
{
    extern __shared__ uint32_t sm[];
    __shared__ float redsum[4][128];
    const uint32_t sbase = (uint32_t)__cvta_generic_to_shared(sm);

    const int tid = threadIdx.x;
    const int lane = tid & 31;
    const int wid = tid >> 5;
    const int wm = wid >> 2, wn = wid & 3;
    const int bh = blockIdx.z;
    const int m0 = blockIdx.y * 128;
    const int n0 = blockIdx.x * 128;

    const __half* Q = g_qh + (size_t)bh * NT * HD;
    const __half* K = g_kh + (size_t)bh * NT * HD;

    stage_tile_h(sbase, Q, m0, HD, 0, tid);
    stage_tile_h(sbase + (uint32_t)4608 * 4, K, n0, HD, 0, tid);
    cp_commit();
    cp_wait<0>();
    __syncthreads();

    float acc[4][4][4] = {};
    compute_tiles16<36>(sm, sm + 4608, wm, wn, lane, acc);

    float rsum[4][2] = {};
    __half* pp = g_p + (size_t)bh * NT * NT;
#pragma unroll
    for (int mt = 0; mt < 4; ++mt) {
        int row = m0 + wm * 64 + mt * 16 + (lane >> 2);
#pragma unroll
        for (int nt = 0; nt < 4; ++nt) {
            int col = n0 + wn * 32 + nt * 8 + ((lane & 3) << 1);
            float e0 = __expf(acc[mt][nt][0] * SCALE);
            float e1 = __expf(acc[mt][nt][1] * SCALE);
            float e2 = __expf(acc[mt][nt][2] * SCALE);
            float e3 = __expf(acc[mt][nt][3] * SCALE);
            *(__half2*)&pp[(size_t)row * NT + col] = __floats2half2_rn(e0, e1);
            *(__half2*)&pp[(size_t)(row + 8) * NT + col] = __floats2half2_rn(e2, e3);
            rsum[mt][0] += e0 + e1;
            rsum[mt][1] += e2 + e3;
        }
    }
#pragma unroll
    for (int off = 1; off < 4; off <<= 1)
#pragma unroll
        for (int mt = 0; mt < 4; ++mt) {
            rsum[mt][0] += __shfl_xor_sync(0xffffffffu, rsum[mt][0], off);
            rsum[mt][1] += __shfl_xor_sync(0xffffffffu, rsum[mt][1], off);
        }
    if ((lane & 3) == 0) {
#pragma unroll
        for (int mt = 0; mt < 4; ++mt) {
            int r = wm * 64 + mt * 16 + (lane >> 2);
            redsum[wn][r] = rsum[mt][0];
            redsum[wn][r + 8] = rsum[mt][1];
        }
    }
    __syncthreads();
    if (tid < 128) {
        float s = redsum[0][tid] + redsum[1][tid] + redsum[2][tid] + redsum[3][tid];
        g_psum[((size_t)bh * NT + m0 + tid) * 8 + blockIdx.x] = s;
    }
}

// ---------------------------------------------------------------------------
// 3) pv: fp16 P + fp16 V(transposed), fp32 attn write, epilogue rinv scaling.
//    grid (8, 96), bh reversed. smem words:
//    Ps[2][2560] (stride 20 w/row) at 0/2560; Vt[2][64*20] at 5120 + buf*1280.
//    Total 7680 w = 30720 B. Output O -> g_xh fp16.
// ---------------------------------------------------------------------------
__global__ __launch_bounds__(256) void pv_kernel(float* __restrict__ attn)
{
    extern __shared__ uint32_t sm[];
    __shared__ float invs[128];
    const uint32_t sbase = (uint32_t)__cvta_generic_to_shared(sm);

    const int tid = threadIdx.x;
    const int lane = tid & 31;
    const int wid = tid >> 5;
    const int wm = wid >> 1, wn = wid & 1;   // warps 4x2, warp tile 32 rows x 32 d
    const int m0 = blockIdx.x * 128;
    const int bh = (NBH - 1) - blockIdx.y;

    for (int r = tid; r < 128; r += 256) {
        const float* pp = &g_psum[((size_t)bh * NT + m0 + r) * 8];
        invs[r] = 1.0f / (pp[0] + pp[1] + pp[2] + pp[3] + pp[4] + pp[5] + pp[6] + pp[7]);
    }
    __syncthreads();

    const __half* Pp = g_p + (size_t)bh * NT * NT;
    float* ap = attn + (size_t)bh * NT * NT;
    const __half* VT = g_vt + (size_t)bh * HD * NT;

    const int srow = tid >> 3;               // 0..31 (+u*32)
    const int sc4 = (tid & 7) * 4;           // col within 32-tile
    float myinv[4];
#pragma unroll
    for (int u = 0; u < 4; ++u) myinv[u] = invs[srow + u * 32];

    float rvf[2][2];
#pragma unroll
    for (int mt = 0; mt < 2; ++mt) {
        rvf[mt][0] = invs[wm * 32 + mt * 16 + (lane >> 2)];
        rvf[mt][1] = invs[wm * 32 + mt * 16 + (lane >> 2) + 8];
    }

    auto stageP = [&](int buf, int k0) {
        uint32_t pofs = sbase + (uint32_t)(buf * 2560) * 4;
#pragma unroll
        for (int u = 0; u < 2; ++u) {
            int idx = tid + u * 256;         // 0..511
            int row = idx >> 2, seg = idx & 3;
            cp16(pofs + (uint32_t)(row * 20 + seg * 4) * 4,
                 &Pp[(size_t)(m0 + row) * NT + k0 + seg * 8]);
        }
    };
    auto stageV = [&](int buf, int k0) {
        uint32_t vofs = sbase + (uint32_t)(5120 + buf * 1280) * 4;
        int d = tid >> 2, seg = tid & 3;
        cp16(vofs + (uint32_t)(d * 20 + seg * 4) * 4,
             &VT[(size_t)d * NT + k0 + seg * 8]);
    };

    stageP(0, 0);
    stageV(0, 0);
    cp_commit();

    float acc[2][4][4] = {};
    for (int kt = 0; kt < 32; ++kt) {
        const int cur = kt & 1;
        if (kt + 1 < 32) {
            stageP((kt + 1) & 1, (kt + 1) * 32);
            stageV((kt + 1) & 1, (kt + 1) * 32);
            cp_commit();
            cp_wait<1>();
        } else cp_wait<0>();
        __syncthreads();

        const uint32_t* Ps = sm + cur * 2560;
        const uint32_t* Vs = sm + 5120 + cur * 1280;

        // write final normalized fp32 attn from fp16 smem
#pragma unroll
        for (int u = 0; u < 4; ++u) {
            int row = srow + u * 32;
            uint2 p2 = *(const uint2*)&Ps[row * 20 + (tid & 7) * 2];
            float2 f0 = __half22float2(*(const __half2*)&p2.x);
            float2 f1 = __half22float2(*(const __half2*)&p2.y);
            float iv = myinv[u];
            float4 v = make_float4(f0.x * iv, f0.y * iv, f1.x * iv, f1.y * iv);
            __stcs((float4*)&ap[(size_t)(m0 + row) * NT + kt * 32 + sc4], v);
        }

        // fp16 mma: O += P_raw V  (2 k16 steps per 32-tile)
#pragma unroll
        for (int ks = 0; ks < 2; ++ks) {
            uint32_t a[2][4], b[4][2];
#pragma unroll
            for (int mt = 0; mt < 2; ++mt) {
                int r = wm * 32 + mt * 16 + (lane >> 2);
                int base = r * 20 + ks * 8 + (lane & 3);
                a[mt][0] = Ps[base];
                a[mt][1] = Ps[base + 160];       // row + 8
                a[mt][2] = Ps[base + 4];         // k + 8
                a[mt][3] = Ps[base + 164];
            }
#pragma unroll
            for (int nt = 0; nt < 4; ++nt) {
                int n = wn * 32 + nt * 8 + (lane >> 2);
                int base = n * 20 + ks * 8 + (lane & 3);
                b[nt][0] = Vs[base];
                b[nt][1] = Vs[base + 4];
            }
#pragma unroll
            for (int mt = 0; mt < 2; ++mt)
#pragma unroll
                for (int nt = 0; nt < 4; ++nt)
                    mma16(acc[mt][nt], a[mt][0], a[mt][1], a[mt][2], a[mt][3],
                          b[nt][0], b[nt][1]);
        }
        __syncthreads();
    }

    const int b = bh / NH, h = bh % NH;
#pragma unroll
    for (int mt = 0; mt < 2; ++mt) {
        int row = m0 + wm * 32 + mt * 16 + (lane >> 2);
#pragma unroll
        for (int nt = 0; nt < 4; ++nt) {
            int d = wn * 32 + nt * 8 + ((lane & 3) << 1);
            *(uint32_t*)&g_xh[((size_t)b * NT + row) * DIM + h * HD + d] =
                h2_as_u32(__floats2half2_rn(acc[mt][nt][0] * rvf[mt][0],
                                            acc[mt][nt][1] * rvf[mt][0]));
            *(uint32_t*)&g_xh[((size_t)b * NT + row + 8) * DIM + h * HD + d] =
                h2_as_u32(__floats2half2_rn(acc[mt][nt][2] * rvf[mt][1],
                                            acc[mt][nt][3] * rvf[mt][1]));
        }
    }
}

// ---------------------------------------------------------------------------
// 4) output projection, fp16 mma, 3-stage cp.async (K=64/stage). grid (6, 64).
// ---------------------------------------------------------------------------
__global__ __launch_bounds__(256, 2) void proj_gemm_kernel(
    const float* __restrict__ bias, float* __restrict__ out)
{
    extern __shared__ uint32_t sm[];
    const uint32_t sbase = (uint32_t)__cvta_generic_to_shared(sm);

    const __half* A = g_xh;
    const __half* W = g_wh + (size_t)3 * DIM * DIM;

    const int tid = threadIdx.x;
    const int lane = tid & 31;
    const int wid = tid >> 5;
    const int wm = wid >> 2, wn = wid & 3;
    const int m0 = blockIdx.y * 128;
    const int n0 = blockIdx.x * 128;

    auto stage = [&](int buf, int k0) {
        stage_tile_h(sbase + (uint32_t)(buf * 4608) * 4, A, m0, DIM, k0, tid);
        stage_tile_h(sbase + (uint32_t)(13824 + buf * 4608) * 4, W, n0, DIM, k0, tid);
        cp_commit();
    };

    float acc[4][4][4] = {};
    stage(0, 0);
    stage(1, 64);
    for (int kt = 0; kt < 12; ++kt) {
        if (kt + 2 < 12) { stage((kt + 2) % 3, (kt + 2) * 64); cp_wait<2>(); }
        else if (kt + 1 < 12) cp_wait<1>();
        else cp_wait<0>();
        __syncthreads();
        compute_tiles16<36>(sm + (kt % 3) * 4608, sm + 13824 + (kt % 3) * 4608,
                            wm, wn, lane, acc);
        __syncthreads();
    }

#pragma unroll
    for (int mt = 0; mt < 4; ++mt) {
        int row = m0 + wm * 64 + mt * 16 + (lane >> 2);
#pragma unroll
        for (int nt = 0; nt < 4; ++nt) {
            int col = n0 + wn * 32 + nt * 8 + ((lane & 3) << 1);
            float bx = bias[col], by = bias[col + 1];
            *(float2*)&out[(size_t)row * DIM + col] =
                make_float2(acc[mt][nt][0] + bx, acc[mt][nt][1] + by);
            *(float2*)&out[(size_t)(row + 8) * DIM + col] =
                make_float2(acc[mt][nt][2] + bx, acc[mt][nt][3] + by);
        }
    }
}

// ---------------------------------------------------------------------------

extern "C" void kernel_launch(void* const* d_in, const int* in_sizes, int n_in,
                              void* d_out, int out_size)
{
    const float* tfeat = (const float*)d_in[0];
    const float* wq = (const float*)d_in[1];
    const float* bq = (const float*)d_in[2];
    const float* wk = (const float*)d_in[3];
    const float* bk = (const float*)d_in[4];
    const float* wv = (const float*)d_in[5];
    const float* bv = (const float*)d_in[6];
    const float* wp = (const float*)d_in[7];
    const float* bp = (const float*)d_in[8];

    float* xout = (float*)d_out;
    float* attn_out = (float*)d_out + (size_t)BATCH * NT * DIM;

    round_all_kernel<<<dim3(1024, 5), 256>>>(tfeat, wq, wk, wv, wp);

    cudaFuncSetAttribute(qkv_gemm_kernel, cudaFuncAttributeMaxDynamicSharedMemorySize, 110592);
    cudaFuncSetAttribute(s_exp_kernel, cudaFuncAttributeMaxDynamicSharedMemorySize, 36864);
    cudaFuncSetAttribute(pv_kernel, cudaFuncAttributeMaxDynamicSharedMemorySize, 30720);
    cudaFuncSetAttribute(proj_gemm_kernel, cudaFuncAttributeMaxDynamicSharedMemorySize, 110592);

    qkv_gemm_kernel<<<dim3(DIM / 128, (BATCH * NT) / 128, 3), 256, 110592>>>(bq, bk, bv);
    s_exp_kernel<<<dim3(NT / 128, NT / 128, NBH), 256, 36864>>>();
    pv_kernel<<<dim3(NT / 128, NBH), 256, 30720>>>(attn_out);
    proj_gemm_kernel<<<dim3(DIM / 128, (BATCH * NT) / 128), 256, 110592>>>(bp, xout);
}

// round 15
// speedup vs baseline: 1.6400x; 1.0274x over previous
#include <cuda_runtime.h>
#include <cuda_fp16.h>
#include <cstdint>

#define BATCH 8
#define NT 1024
#define DIM 768
#define NH 12
#define HD 64
#define SCALE 0.125f
#define NBH (BATCH * NH)

// scratch (allocation-free rule: __device__ globals)
__device__ __half g_qh[NBH * NT * HD];                // Q fp16 [bh][t][d]
__device__ __half g_kh[NBH * NT * HD];                // K fp16 [bh][t][d]
__device__ __half g_vt[NBH * HD * NT];                // V fp16 transposed [bh][d][t]
__device__ __half g_xh[BATCH * NT * DIM];             // attention output, fp16
__device__ __half g_tfh[BATCH * NT * DIM];            // fp16 tfeat
__device__ __half g_wh[4 * DIM * DIM];                // fp16 wq,wk,wv,wp
__device__ __half g_p[(size_t)NBH * NT * NT];         // unnormalized exp scores, fp16

// ---------------------------------------------------------------------------
// helpers
// ---------------------------------------------------------------------------
__device__ __forceinline__ uint32_t h2_as_u32(__half2 h) {
    union { __half2 h2; uint32_t u; } cvt;
    cvt.h2 = h;
    return cvt.u;
}

__device__ __forceinline__ void cp16(uint32_t s, const void* g) {
    asm volatile("cp.async.cg.shared.global [%0], [%1], 16;" :: "r"(s), "l"(g));
}
__device__ __forceinline__ void cp_commit() { asm volatile("cp.async.commit_group;"); }
template <int N> __device__ __forceinline__ void cp_wait() {
    asm volatile("cp.async.wait_group %0;" :: "n"(N));
}

__device__ __forceinline__ void mma16(float* c,
                                      uint32_t a0, uint32_t a1, uint32_t a2, uint32_t a3,
                                      uint32_t b0, uint32_t b1) {
    asm volatile(
        "mma.sync.aligned.m16n8k16.row.col.f32.f16.f16.f32 "
        "{%0,%1,%2,%3},{%4,%5,%6,%7},{%8,%9},{%0,%1,%2,%3};"
        : "+f"(c[0]), "+f"(c[1]), "+f"(c[2]), "+f"(c[3])
        : "r"(a0), "r"(a1), "r"(a2), "r"(a3), "r"(b0), "r"(b1));
}

// fp16 128x128 block, K=64 (4 k16 steps), operands at word-stride STRIDE
template <int STRIDE>
__device__ __forceinline__ void compute_tiles16(const uint32_t* __restrict__ As,
                                                const uint32_t* __restrict__ Bs,
                                                int wm, int wn, int lane,
                                                float acc[4][4][4]) {
#pragma unroll
    for (int ks = 0; ks < 4; ++ks) {
        const int col = ks * 8 + (lane & 3);
        uint32_t a[4][4], b[4][2];
#pragma unroll
        for (int mt = 0; mt < 4; ++mt) {
            int r = wm * 64 + mt * 16 + (lane >> 2);
            a[mt][0] = As[r * STRIDE + col];
            a[mt][1] = As[(r + 8) * STRIDE + col];
            a[mt][2] = As[r * STRIDE + col + 4];
            a[mt][3] = As[(r + 8) * STRIDE + col + 4];
        }
#pragma unroll
        for (int nt = 0; nt < 4; ++nt) {
            int n = wn * 32 + nt * 8 + (lane >> 2);
            b[nt][0] = Bs[n * STRIDE + col];
            b[nt][1] = Bs[n * STRIDE + col + 4];
        }
#pragma unroll
        for (int mt = 0; mt < 4; ++mt)
#pragma unroll
            for (int nt = 0; nt < 4; ++nt)
                mma16(acc[mt][nt], a[mt][0], a[mt][1], a[mt][2], a[mt][3],
                      b[nt][0], b[nt][1]);
    }
}

// ---------------------------------------------------------------------------
// 0) fp16 pre-rounding, one launch
// ---------------------------------------------------------------------------
__global__ void round_all_kernel(const float* __restrict__ tfeat,
                                 const float* __restrict__ wq,
                                 const float* __restrict__ wk,
                                 const float* __restrict__ wv,
                                 const float* __restrict__ wp) {
    const int y = blockIdx.y;
    const float* src;
    __half* dst;
    int n4;
    if (y == 0) { src = tfeat; dst = g_tfh; n4 = BATCH * NT * DIM / 4; }
    else {
        src = (y == 1) ? wq : (y == 2) ? wk : (y == 3) ? wv : wp;
        dst = g_wh + (size_t)(y - 1) * DIM * DIM;
        n4 = DIM * DIM / 4;
    }
    for (int i = blockIdx.x * blockDim.x + threadIdx.x; i < n4;
         i += gridDim.x * blockDim.x) {
        float4 v = ((const float4*)src)[i];
        uint2 o;
        o.x = h2_as_u32(__floats2half2_rn(v.x, v.y));
        o.y = h2_as_u32(__floats2half2_rn(v.z, v.w));
        ((uint2*)dst)[i] = o;
    }
}

// stage a 128-row x 64-half tile (stride 36 words) -- 8 cp16s per row
__device__ __forceinline__ void stage_tile_h(uint32_t dst_base, const __half* src,
                                             int row0, int ld, int k0, int tid) {
#pragma unroll
    for (int u = 0; u < 4; ++u) {
        int idx = tid + u * 256;         // 0..1023
        int row = idx >> 3;              // 0..127
        int seg = idx & 7;               // 0..7, 8 halves each
        cp16(dst_base + (uint32_t)(row * 36 + seg * 4) * 4,
             &src[(size_t)(row0 + row) * ld + k0 + seg * 8]);
    }
}

// ---------------------------------------------------------------------------
// 1) QKV projection, fp16 mma, 3-stage cp.async (K=64/stage). grid (6, 64, 3).
// ---------------------------------------------------------------------------
__global__ __launch_bounds__(256, 2) void qkv_gemm_kernel(
    const float* __restrict__ bq, const float* __restrict__ bk,
    const float* __restrict__ bv)
{
    extern __shared__ uint32_t sm[];
    const uint32_t sbase = (uint32_t)__cvta_generic_to_shared(sm);

    const int z = blockIdx.z;
    const __half* A = g_tfh;
    const __half* W = g_wh + (size_t)z * DIM * DIM;
    const float* bias = (z == 0) ? bq : (z == 1) ? bk : bv;

    const int tid = threadIdx.x;
    const int lane = tid & 31;
    const int wid = tid >> 5;
    const int wm = wid >> 2, wn = wid & 3;
    const int m0 = blockIdx.y * 128;
    const int n0 = blockIdx.x * 128;

    auto stage = [&](int buf, int k0) {
        stage_tile_h(sbase + (uint32_t)(buf * 4608) * 4, A, m0, DIM, k0, tid);
        stage_tile_h(sbase + (uint32_t)(13824 + buf * 4608) * 4, W, n0, DIM, k0, tid);
        cp_commit();
    };

    float acc[4][4][4] = {};
    stage(0, 0);
    stage(1, 64);
    for (int kt = 0; kt < 12; ++kt) {
        if (kt + 2 < 12) { stage((kt + 2) % 3, (kt + 2) * 64); cp_wait<2>(); }
        else if (kt + 1 < 12) cp_wait<1>();
        else cp_wait<0>();
        __syncthreads();
        compute_tiles16<36>(sm + (kt % 3) * 4608, sm + 13824 + (kt % 3) * 4608,
                            wm, wn, lane, acc);
        __syncthreads();
    }

    if (z < 2) {
        __half* out = (z == 0) ? g_qh : g_kh;
#pragma unroll
        for (int mt = 0; mt < 4; ++mt) {
            int row = m0 + wm * 64 + mt * 16 + (lane >> 2);
            int b0i = row >> 10, t0 = row & 1023;
#pragma unroll
            for (int nt = 0; nt < 4; ++nt) {
                int col = n0 + wn * 32 + nt * 8 + ((lane & 3) << 1);
                int h = col >> 6, d = col & 63;
                float bx = bias[col], by = bias[col + 1];
                *(uint32_t*)&out[((size_t)(b0i * NH + h) * NT + t0) * HD + d] =
                    h2_as_u32(__floats2half2_rn(acc[mt][nt][0] + bx, acc[mt][nt][1] + by));
                *(uint32_t*)&out[((size_t)(b0i * NH + h) * NT + t0 + 8) * HD + d] =
                    h2_as_u32(__floats2half2_rn(acc[mt][nt][2] + bx, acc[mt][nt][3] + by));
            }
        }
    } else {
        // transpose through smem: T[t_local][d_local], stride 133 (fp32)
        __syncthreads();
        float* T = (float*)sm;
#pragma unroll
        for (int mt = 0; mt < 4; ++mt) {
            int lr = wm * 64 + mt * 16 + (lane >> 2);
#pragma unroll
            for (int nt = 0; nt < 4; ++nt) {
                int lc = wn * 32 + nt * 8 + ((lane & 3) << 1);
                float bx = bias[n0 + lc], by = bias[n0 + lc + 1];
                T[lr * 133 + lc]           = acc[mt][nt][0] + bx;
                T[lr * 133 + lc + 1]       = acc[mt][nt][1] + by;
                T[(lr + 8) * 133 + lc]     = acc[mt][nt][2] + bx;
                T[(lr + 8) * 133 + lc + 1] = acc[mt][nt][3] + by;
            }
        }
        __syncthreads();
        const int b0i = m0 >> 10;
        const int t00 = m0 & 1023;
#pragma unroll
        for (int u = 0; u < 16; ++u) {
            int idx = tid + u * 256;
            int dcol = idx >> 5;
            int tq = (idx & 31) << 2;
            uint2 v;
            v.x = h2_as_u32(__floats2half2_rn(T[(tq + 0) * 133 + dcol], T[(tq + 1) * 133 + dcol]));
            v.y = h2_as_u32(__floats2half2_rn(T[(tq + 2) * 133 + dcol], T[(tq + 3) * 133 + dcol]));
            int h = (n0 + dcol) >> 6, d = (n0 + dcol) & 63;
            *(uint2*)&g_vt[((size_t)(b0i * NH + h) * HD + d) * NT + t00 + tq] = v;
        }
    }
}

// ---------------------------------------------------------------------------
// 2) merged attention: one block owns a 128-row stripe of one bh.
//    Phase 1: S = exp(QK^T*SCALE) -> g_p (plain stores, stays in L2),
//             row sums in registers -> invs (no inter-block dependency).
//    Phase 2: re-read own P stripe (L2 hits), write fp32 attn once, PV mma.
//    grid (8, 96). smem words: phase1 K[2] at 0/4608, Q at 9216 (13824 w);
//    phase2 reuses: P[2] at 0/2560, V[2] at 5120 + buf*1280.
//    Total 55296 B dynamic.
// ---------------------------------------------------------------------------
__global__ __launch_bounds__(256) void attn_kernel(float* __restrict__ attn)
{
    extern __shared__ uint32_t sm[];
    __shared__ float redsum[4][128];
    __shared__ float invs[128];
    const uint32_t sbase = (uint32_t)__cvta_generic_to_shared(sm);

    const int tid = threadIdx.x;
    const int lane = tid & 31;
    const int wid = tid >> 5;
    const int m0 = blockIdx.x * 128;
    const int bh = blockIdx.y;

    const __half* Q = g_qh + (size_t)bh * NT * HD;
    const __half* K = g_kh + (size_t)bh * NT * HD;
    const __half* VT = g_vt + (size_t)bh * HD * NT;
    __half* Pp = g_p + (size_t)bh * NT * NT;
    float* ap = attn + (size_t)bh * NT * NT;

    // ======================= phase 1: scores + rowsums ======================
    {
        const int wm = wid >> 2, wn = wid & 3;   // 2x4 layout, warp tile 64x32
        const uint32_t qofs = sbase + (uint32_t)9216 * 4;

        stage_tile_h(qofs, Q, m0, HD, 0, tid);
        stage_tile_h(sbase, K, 0, HD, 0, tid);
        cp_commit();

        float rsum[4][2] = {};
        for (int ct = 0; ct < 8; ++ct) {
            if (ct + 1 < 8) {
                stage_tile_h(sbase + (uint32_t)(((ct + 1) & 1) * 4608) * 4,
                             K, (ct + 1) * 128, HD, 0, tid);
                cp_commit();
                cp_wait<1>();
            } else cp_wait<0>();
            __syncthreads();

            float acc[4][4][4] = {};
            compute_tiles16<36>(sm + 9216, sm + (ct & 1) * 4608, wm, wn, lane, acc);

            const int n0 = ct * 128;
#pragma unroll
            for (int mt = 0; mt < 4; ++mt) {
                int row = m0 + wm * 64 + mt * 16 + (lane >> 2);
#pragma unroll
                for (int nt = 0; nt < 4; ++nt) {
                    int col = n0 + wn * 32 + nt * 8 + ((lane & 3) << 1);
                    float e0 = __expf(acc[mt][nt][0] * SCALE);
                    float e1 = __expf(acc[mt][nt][1] * SCALE);
                    float e2 = __expf(acc[mt][nt][2] * SCALE);
                    float e3 = __expf(acc[mt][nt][3] * SCALE);
                    *(__half2*)&Pp[(size_t)row * NT + col] = __floats2half2_rn(e0, e1);
                    *(__half2*)&Pp[(size_t)(row + 8) * NT + col] = __floats2half2_rn(e2, e3);
                    rsum[mt][0] += e0 + e1;
                    rsum[mt][1] += e2 + e3;
                }
            }
            __syncthreads();
        }

#pragma unroll
        for (int off = 1; off < 4; off <<= 1)
#pragma unroll
            for (int mt = 0; mt < 4; ++mt) {
                rsum[mt][0] += __shfl_xor_sync(0xffffffffu, rsum[mt][0], off);
                rsum[mt][1] += __shfl_xor_sync(0xffffffffu, rsum[mt][1], off);
            }
        if ((lane & 3) == 0) {
#pragma unroll
            for (int mt = 0; mt < 4; ++mt) {
                int r = wm * 64 + mt * 16 + (lane >> 2);
                redsum[wn][r] = rsum[mt][0];
                redsum[wn][r + 8] = rsum[mt][1];
            }
        }
        __syncthreads();
        if (tid < 128)
            invs[tid] = 1.0f / (redsum[0][tid] + redsum[1][tid] + redsum[2][tid] + redsum[3][tid]);
        __syncthreads();
    }

    // ======================= phase 2: attn write + PV =======================
    const int wm = wid >> 1, wn = wid & 1;       // 4x2 layout, warp tile 32x32

    const int srow = tid >> 3;                   // 0..31 (+u*32)
    const int sc4 = (tid & 7) * 4;
    float myinv[4];
#pragma unroll
    for (int u = 0; u < 4; ++u) myinv[u] = invs[srow + u * 32];

    float rvf[2][2];
#pragma unroll
    for (int mt = 0; mt < 2; ++mt) {
        rvf[mt][0] = invs[wm * 32 + mt * 16 + (lane >> 2)];
        rvf[mt][1] = invs[wm * 32 + mt * 16 + (lane >> 2) + 8];
    }

    auto stageP = [&](int buf, int k0) {
        uint32_t pofs = sbase + (uint32_t)(buf * 2560) * 4;
#pragma unroll
        for (int u = 0; u < 2; ++u) {
            int idx = tid + u * 256;
            int row = idx >> 2, seg = idx & 3;
            cp16(pofs + (uint32_t)(row * 20 + seg * 4) * 4,
                 &Pp[(size_t)(m0 + row) * NT + k0 + seg * 8]);
        }
    };
    auto stageV = [&](int buf, int k0) {
        uint32_t vofs = sbase + (uint32_t)(5120 + buf * 1280) * 4;
        int d = tid >> 2, seg = tid & 3;
        cp16(vofs + (uint32_t)(d * 20 + seg * 4) * 4,
             &VT[(size_t)d * NT + k0 + seg * 8]);
    };

    stageP(0, 0);
    stageV(0, 0);
    cp_commit();

    float acc[2][4][4] = {};
    for (int kt = 0; kt < 32; ++kt) {
        const int cur = kt & 1;
        if (kt + 1 < 32) {
            stageP((kt + 1) & 1, (kt + 1) * 32);
            stageV((kt + 1) & 1, (kt + 1) * 32);
            cp_commit();
            cp_wait<1>();
        } else cp_wait<0>();
        __syncthreads();

        const uint32_t* Ps = sm + cur * 2560;
        const uint32_t* Vs = sm + 5120 + cur * 1280;

        // write final normalized fp32 attn from fp16 smem
#pragma unroll
        for (int u = 0; u < 4; ++u) {
            int row = srow + u * 32;
            uint2 p2 = *(const uint2*)&Ps[row * 20 + (tid & 7) * 2];
            float2 f0 = __half22float2(*(const __half2*)&p2.x);
            float2 f1 = __half22float2(*(const __half2*)&p2.y);
            float iv = myinv[u];
            float4 v = make_float4(f0.x * iv, f0.y * iv, f1.x * iv, f1.y * iv);
            __stcs((float4*)&ap[(size_t)(m0 + row) * NT + kt * 32 + sc4], v);
        }

        // fp16 mma: O += P_raw V  (2 k16 steps per 32-tile)
#pragma unroll
        for (int ks = 0; ks < 2; ++ks) {
            uint32_t a[2][4], b[4][2];
#pragma unroll
            for (int mt = 0; mt < 2; ++mt) {
                int r = wm * 32 + mt * 16 + (lane >> 2);
                int base = r * 20 + ks * 8 + (lane & 3);
                a[mt][0] = Ps[base];
                a[mt][1] = Ps[base + 160];
                a[mt][2] = Ps[base + 4];
                a[mt][3] = Ps[base + 164];
            }
#pragma unroll
            for (int nt = 0; nt < 4; ++nt) {
                int n = wn * 32 + nt * 8 + (lane >> 2);
                int base = n * 20 + ks * 8 + (lane & 3);
                b[nt][0] = Vs[base];
                b[nt][1] = Vs[base + 4];
            }
#pragma unroll
            for (int mt = 0; mt < 2; ++mt)
#pragma unroll
                for (int nt = 0; nt < 4; ++nt)
                    mma16(acc[mt][nt], a[mt][0], a[mt][1], a[mt][2], a[mt][3],
                          b[nt][0], b[nt][1]);
        }
        __syncthreads();
    }

    const int b = bh / NH, h = bh % NH;
#pragma unroll
    for (int mt = 0; mt < 2; ++mt) {
        int row = m0 + wm * 32 + mt * 16 + (lane >> 2);
#pragma unroll
        for (int nt = 0; nt < 4; ++nt) {
            int d = wn * 32 + nt * 8 + ((lane & 3) << 1);
            *(uint32_t*)&g_xh[((size_t)b * NT + row) * DIM + h * HD + d] =
                h2_as_u32(__floats2half2_rn(acc[mt][nt][0] * rvf[mt][0],
                                            acc[mt][nt][1] * rvf[mt][0]));
            *(uint32_t*)&g_xh[((size_t)b * NT + row + 8) * DIM + h * HD + d] =
                h2_as_u32(__floats2half2_rn(acc[mt][nt][2] * rvf[mt][1],
                                            acc[mt][nt][3] * rvf[mt][1]));
        }
    }
}

// ---------------------------------------------------------------------------
// 3) output projection, fp16 mma, 3-stage cp.async (K=64/stage). grid (6, 64).
// ---------------------------------------------------------------------------
__global__ __launch_bounds__(256, 2) void proj_gemm_kernel(
    const float* __restrict__ bias, float* __restrict__ out)
{
    extern __shared__ uint32_t sm[];
    const uint32_t sbase = (uint32_t)__cvta_generic_to_shared(sm);

    const __half* A = g_xh;
    const __half* W = g_wh + (size_t)3 * DIM * DIM;

    const int tid = threadIdx.x;
    const int lane = tid & 31;
    const int wid = tid >> 5;
    const int wm = wid >> 2, wn = wid & 3;
    const int m0 = blockIdx.y * 128;
    const int n0 = blockIdx.x * 128;

    auto stage = [&](int buf, int k0) {
        stage_tile_h(sbase + (uint32_t)(buf * 4608) * 4, A, m0, DIM, k0, tid);
        stage_tile_h(sbase + (uint32_t)(13824 + buf * 4608) * 4, W, n0, DIM, k0, tid);
        cp_commit();
    };

    float acc[4][4][4] = {};
    stage(0, 0);
    stage(1, 64);
    for (int kt = 0; kt < 12; ++kt) {
        if (kt + 2 < 12) { stage((kt + 2) % 3, (kt + 2) * 64); cp_wait<2>(); }
        else if (kt + 1 < 12) cp_wait<1>();
        else cp_wait<0>();
        __syncthreads();
        compute_tiles16<36>(sm + (kt % 3) * 4608, sm + 13824 + (kt % 3) * 4608,
                            wm, wn, lane, acc);
        __syncthreads();
    }

#pragma unroll
    for (int mt = 0; mt < 4; ++mt) {
        int row = m0 + wm * 64 + mt * 16 + (lane >> 2);
#pragma unroll
        for (int nt = 0; nt < 4; ++nt) {
            int col = n0 + wn * 32 + nt * 8 + ((lane & 3) << 1);
            float bx = bias[col], by = bias[col + 1];
            *(float2*)&out[(size_t)row * DIM + col] =
                make_float2(acc[mt][nt][0] + bx, acc[mt][nt][1] + by);
            *(float2*)&out[(size_t)(row + 8) * DIM + col] =
                make_float2(acc[mt][nt][2] + bx, acc[mt][nt][3] + by);
        }
    }
}

// ---------------------------------------------------------------------------

extern "C" void kernel_launch(void* const* d_in, const int* in_sizes, int n_in,
                              void* d_out, int out_size)
{
    const float* tfeat = (const float*)d_in[0];
    const float* wq = (const float*)d_in[1];
    const float* bq = (const float*)d_in[2];
    const float* wk = (const float*)d_in[3];
    const float* bk = (const float*)d_in[4];
    const float* wv = (const float*)d_in[5];
    const float* bv = (const float*)d_in[6];
    const float* wp = (const float*)d_in[7];
    const float* bp = (const float*)d_in[8];

    float* xout = (float*)d_out;
    float* attn_out = (float*)d_out + (size_t)BATCH * NT * DIM;

    round_all_kernel<<<dim3(1024, 5), 256>>>(tfeat, wq, wk, wv, wp);

    cudaFuncSetAttribute(qkv_gemm_kernel, cudaFuncAttributeMaxDynamicSharedMemorySize, 110592);
    cudaFuncSetAttribute(attn_kernel, cudaFuncAttributeMaxDynamicSharedMemorySize, 55296);
    cudaFuncSetAttribute(proj_gemm_kernel, cudaFuncAttributeMaxDynamicSharedMemorySize, 110592);

    qkv_gemm_kernel<<<dim3(DIM / 128, (BATCH * NT) / 128, 3), 256, 110592>>>(bq, bk, bv);
    attn_kernel<<<dim3(NT / 128, NBH), 256, 55296>>>(attn_out);
    proj_gemm_kernel<<<dim3(DIM / 128, (BATCH * NT) / 128), 256, 110592>>>(bp, xout);
}